// round 1
// baseline (speedup 1.0000x reference)
#include <cuda_runtime.h>

#define H0c 100
#define W0c 152
#define H1c 50
#define W1c 76
#define HW0 (H0c*W0c)          // 15200
#define HW1 (H1c*W1c)          // 3800
#define NB 2
#define CIN 256
#define DYNC 34
#define CLSC 720
#define NCLS 80

// level-1 offsets into scratch
#define PRED_OFF1 (NB*HW0*DYNC)     // 1,033,600
#define REG_OFF1  (NB*HW0*4)        // 121,600
#define CLS_OFF1  ((size_t)NB*HW0*CLSC) // 21,888,000

// output offsets (floats)
#define O_CLS0 0
#define O_CLS1 (NB*NCLS*HW0)                    // 2,432,000
#define O_CO0  (O_CLS1 + NB*NCLS*HW1)           // 3,040,000
#define O_CO1  (O_CO0 + NB*4*HW0)               // 3,161,600
#define O_RB0  (O_CO1 + NB*4*HW1)               // 3,192,000
#define O_RB1  (O_RB0 + NB*4*HW0)               // 3,313,600

// ---------------- scratch (device globals; no runtime alloc) ----------------
__device__ float g_pred[NB*(HW0+HW1)*DYNC];     // NHWC per-level: [pix][34]
__device__ float g_regmap[NB*(HW0+HW1)*4];      // [pix][4]
__device__ float g_clsmap[(size_t)NB*(HW0+HW1)*CLSC]; // [pix][720]
__device__ __align__(16) float g_wdynT[CIN*DYNC*12];  // [c][o][12] (9 used)
__device__ float g_wclsT[CIN*CLSC];             // [c][oc]

// ---------------- weight prep ----------------
__global__ void prep_dyn_kernel(const float* __restrict__ dyn_w) {
    int i = blockIdx.x*blockDim.x + threadIdx.x;
    if (i < DYNC*CIN*9) {
        int o = i / (CIN*9);
        int r = i - o*CIN*9;
        int c = r / 9;
        int k = r - c*9;
        g_wdynT[(c*DYNC + o)*12 + k] = dyn_w[i];
    }
}

__global__ void prep_cls_kernel(const float* __restrict__ cls_w) {
    int i = blockIdx.x*blockDim.x + threadIdx.x;
    if (i < CLSC*CIN) {
        int oc = i / CIN;
        int c  = i - oc*CIN;
        g_wclsT[c*CLSC + oc] = cls_w[i];
    }
}

// ---------------- fused 3x3 dyn conv + 1x1 reg conv ----------------
// block (32,8) = one 32x8 pixel tile; each thread: 34 dyn accs + 4 reg accs
__global__ void __launch_bounds__(256) dyn_conv_kernel(
    const float* __restrict__ in,      // [N][256][H][W]
    const float* __restrict__ reg_w,   // [4][256]
    const float* __restrict__ dyn_b,   // [34]
    int H, int W, int predOff, int regOff)
{
    __shared__ __align__(16) float tile[10*34];
    __shared__ __align__(16) float ws[DYNC*12];
    __shared__ float wr[4];
    __shared__ float bs[DYNC];

    int tx = threadIdx.x, ty = threadIdx.y;
    int tid = ty*32 + tx;
    int n  = blockIdx.z;
    int gx0 = blockIdx.x*32, gy0 = blockIdx.y*8;
    int gx = gx0 + tx, gy = gy0 + ty;
    int HW = H*W;

    if (tid < DYNC) bs[tid] = dyn_b[tid];

    float acc[DYNC];
    #pragma unroll
    for (int o = 0; o < DYNC; o++) acc[o] = 0.f;
    float r0 = 0.f, r1 = 0.f, r2 = 0.f, r3 = 0.f;

    const float* inN = in + (size_t)n*CIN*HW;

    for (int c = 0; c < CIN; c++) {
        __syncthreads();
        for (int idx = tid; idx < 340; idx += 256) {
            int rr = idx / 34;
            int cc = idx - rr*34;
            int iy = gy0 + rr - 1;
            int ix = gx0 + cc - 1;
            tile[idx] = (iy >= 0 && iy < H && ix >= 0 && ix < W)
                        ? inN[(size_t)c*HW + iy*W + ix] : 0.f;
        }
        for (int idx = tid; idx < DYNC*12; idx += 256)
            ws[idx] = g_wdynT[c*DYNC*12 + idx];
        if (tid < 4) wr[tid] = reg_w[tid*CIN + c];
        __syncthreads();

        float v[9];
        #pragma unroll
        for (int dy = 0; dy < 3; dy++)
            #pragma unroll
            for (int dx = 0; dx < 3; dx++)
                v[dy*3+dx] = tile[(ty+dy)*34 + tx + dx];

        #pragma unroll
        for (int o = 0; o < DYNC; o++) {
            float4 wa = *(const float4*)&ws[o*12];
            float4 wb = *(const float4*)&ws[o*12 + 4];
            float  w8 = ws[o*12 + 8];
            float a = acc[o];
            a = fmaf(wa.x, v[0], a);
            a = fmaf(wa.y, v[1], a);
            a = fmaf(wa.z, v[2], a);
            a = fmaf(wa.w, v[3], a);
            a = fmaf(wb.x, v[4], a);
            a = fmaf(wb.y, v[5], a);
            a = fmaf(wb.z, v[6], a);
            a = fmaf(wb.w, v[7], a);
            a = fmaf(w8,   v[8], a);
            acc[o] = a;
        }
        float cv = v[4];
        r0 = fmaf(wr[0], cv, r0);
        r1 = fmaf(wr[1], cv, r1);
        r2 = fmaf(wr[2], cv, r2);
        r3 = fmaf(wr[3], cv, r3);
    }

    if (gx < W && gy < H) {
        size_t pix = (size_t)n*HW + (size_t)gy*W + gx;
        float* pp = g_pred + predOff + pix*DYNC;
        #pragma unroll
        for (int o = 0; o < DYNC; o++) pp[o] = acc[o] + bs[o];
        *(float4*)&g_regmap[regOff + pix*4] = make_float4(r0, r1, r2, r3);
    }
}

// ---------------- cls 1x1 conv: GEMM 720x256 over pixels ----------------
// BM=128 pix, BN=64 oc, BK=16; 256 threads; 8x4 micro-tile
__global__ void __launch_bounds__(256) cls_gemm_kernel(
    const float* __restrict__ in,   // [N][256][HW]
    int HW, size_t clsOff)
{
    __shared__ __align__(16) float As[16*128];
    __shared__ __align__(16) float Bs[16*64];

    int t = threadIdx.x;
    int txp = t & 15;   // pixel group -> pixels txp*8 .. +7
    int typ = t >> 4;   // oc group    -> ocs typ*4 .. +3
    int n = blockIdx.z;
    int pixbase = blockIdx.x*128;
    int ocbase  = blockIdx.y*64;

    const float* inN = in + (size_t)n*CIN*HW;

    float acc[8][4];
    #pragma unroll
    for (int i = 0; i < 8; i++)
        #pragma unroll
        for (int j = 0; j < 4; j++) acc[i][j] = 0.f;

    for (int kt = 0; kt < CIN; kt += 16) {
        #pragma unroll
        for (int i = 0; i < 8; i++) {
            int idx = t + i*256;
            int k = idx >> 7;
            int m = idx & 127;
            int pix = pixbase + m;
            As[idx] = (pix < HW) ? inN[(size_t)(kt + k)*HW + pix] : 0.f;
        }
        #pragma unroll
        for (int i = 0; i < 4; i++) {
            int idx = t + i*256;
            int k = idx >> 6;
            int oc = ocbase + (idx & 63);
            Bs[idx] = (oc < CLSC) ? g_wclsT[(kt + k)*CLSC + oc] : 0.f;
        }
        __syncthreads();

        #pragma unroll
        for (int k = 0; k < 16; k++) {
            float4 a0 = *(const float4*)&As[k*128 + txp*8];
            float4 a1 = *(const float4*)&As[k*128 + txp*8 + 4];
            float4 b  = *(const float4*)&Bs[k*64 + typ*4];
            float av[8] = {a0.x,a0.y,a0.z,a0.w,a1.x,a1.y,a1.z,a1.w};
            float bv[4] = {b.x,b.y,b.z,b.w};
            #pragma unroll
            for (int i = 0; i < 8; i++)
                #pragma unroll
                for (int j = 0; j < 4; j++)
                    acc[i][j] = fmaf(av[i], bv[j], acc[i][j]);
        }
        __syncthreads();
    }

    float* cm = g_clsmap + clsOff + (size_t)n*HW*CLSC;
    int oc = ocbase + typ*4;
    if (oc < CLSC) {
        #pragma unroll
        for (int i = 0; i < 8; i++) {
            int pix = pixbase + txp*8 + i;
            if (pix < HW) {
                *(float4*)&cm[(size_t)pix*CLSC + oc] =
                    make_float4(acc[i][0], acc[i][1], acc[i][2], acc[i][3]);
            }
        }
    }
}

// ---------------- geometry + reg sampling ----------------
__device__ __forceinline__ float bilin4(const float* __restrict__ rm,
                                        int H, int W, float px, float py, int ch)
{
    px = fminf(fmaxf(px, 0.f), (float)(W - 1));
    py = fminf(fmaxf(py, 0.f), (float)(H - 1));
    float xf = floorf(px), yf = floorf(py);
    float fx = px - xf, fy = py - yf;
    int x0 = (int)xf, y0 = (int)yf;
    int x1 = min(x0 + 1, W - 1), y1 = min(y0 + 1, H - 1);
    float v00 = rm[(y0*W + x0)*4 + ch];
    float v01 = rm[(y0*W + x1)*4 + ch];
    float v10 = rm[(y1*W + x0)*4 + ch];
    float v11 = rm[(y1*W + x1)*4 + ch];
    return v00*(1.f-fx)*(1.f-fy) + v01*fx*(1.f-fy)
         + v10*(1.f-fx)*fy       + v11*fx*fy;
}

__global__ void geom_kernel(const float* __restrict__ anchor,  // [N][4][H][W]
                            int H, int W, int predOff, int regOff, int isL1,
                            float* __restrict__ out_coarse,
                            float* __restrict__ out_regbox)
{
    int t = blockIdx.x*blockDim.x + threadIdx.x;
    int HW = H*W;
    if (t >= NB*HW) return;
    int n = t / HW;
    int rem = t - n*HW;

    const float* p = g_pred + predOff + (size_t)t*DYNC;
    float x1b = anchor[(n*4 + 0)*HW + rem] + p[0];
    float y1b = anchor[(n*4 + 1)*HW + rem] + p[1];
    float x2b = anchor[(n*4 + 2)*HW + rem] + p[2];
    float y2b = anchor[(n*4 + 3)*HW + rem] + p[3];
    float cx = 0.5f*(x1b + x2b), cy = 0.5f*(y1b + y2b);
    float th_h = (y2b - y1b)*0.25f;  // /2 * RATIO(0.5)
    float th_w = (x2b - x1b)*0.25f;
    float b0 = p[4], b1 = p[5], b2 = p[6], b3 = p[7];
    float bc0 = b0 - (fmaxf(b0 - th_h, 0.f) + fminf(b0 + th_h, 0.f));
    float bc1 = b1 - (fmaxf(b1 - th_w, 0.f) + fminf(b1 + th_w, 0.f));
    float bc2 = b2 - (fmaxf(b2 - th_h, 0.f) + fminf(b2 + th_h, 0.f));
    float bc3 = b3 - (fmaxf(b3 - th_w, 0.f) + fminf(b3 + th_w, 0.f));

    // bound points: p0=(x1, cy+bc0) p1=(cx+bc1, y1) p2=(x2, cy+bc2) p3=(cx+bc3, y2)
    float ptx[4] = {x1b, cx + bc1, x2b, cx + bc3};
    float pty[4] = {cy + bc0, y1b, cy + bc2, y2b};

    const float* rm = g_regmap + regOff + (size_t)n*HW*4;
    float r[4];
    #pragma unroll
    for (int pc = 0; pc < 4; pc++)
        r[pc] = bilin4(rm, H, W, ptx[pc], pty[pc], pc);

    if (isL1) {
        const float* rml = g_regmap + (size_t)n*HW0*4;  // level-0 regmap
        #pragma unroll
        for (int pc = 0; pc < 4; pc++) {
            float rl = 0.5f*bilin4(rml, H0c, W0c, 2.f*ptx[pc], 2.f*pty[pc], pc);
            float al = p[26 + 2*pc], ah = p[27 + 2*pc];
            float m = fmaxf(al, ah);
            float el = expf(al - m), eh = expf(ah - m);
            float inv = 1.f/(el + eh);
            r[pc] = (el*rl + eh*r[pc])*inv;
        }
    }

    out_coarse[(n*4 + 0)*HW + rem] = x1b;
    out_coarse[(n*4 + 1)*HW + rem] = y1b;
    out_coarse[(n*4 + 2)*HW + rem] = x2b;
    out_coarse[(n*4 + 3)*HW + rem] = y2b;
    out_regbox[(n*4 + 0)*HW + rem] = x1b + r[0];
    out_regbox[(n*4 + 1)*HW + rem] = y1b + r[1];
    out_regbox[(n*4 + 2)*HW + rem] = x2b + r[2];
    out_regbox[(n*4 + 3)*HW + rem] = y2b + r[3];
}

// ---------------- cls sampling: 1 block = 1 pixel, 80 threads = 80 classes ----------------
__global__ void cls_sample_kernel(const float* __restrict__ coarse,   // [N][4][H][W]
                                  const float* __restrict__ cls_b,    // [80]
                                  int H, int W, int predOff, size_t clsOff,
                                  float* __restrict__ out)            // [N][80][H][W]
{
    int t = blockIdx.x;
    int HW = H*W;
    int n = t / HW;
    int rem = t - n*HW;

    const float* p = g_pred + predOff + (size_t)t*DYNC;
    float x1b = coarse[(n*4 + 0)*HW + rem];
    float y1b = coarse[(n*4 + 1)*HW + rem];
    float x2b = coarse[(n*4 + 2)*HW + rem];
    float y2b = coarse[(n*4 + 3)*HW + rem];
    float X[3] = {x1b, 0.5f*(x1b + x2b), x2b};
    float Y[3] = {y1b, 0.5f*(y1b + y2b), y2b};

    int cls = threadIdx.x;
    float acc = cls_b[cls];
    const float* cm = g_clsmap + clsOff + (size_t)n*HW*CLSC;

    #pragma unroll
    for (int pt = 0; pt < 9; pt++) {
        float px = X[pt/3] + p[8 + 2*pt];
        float py = Y[pt%3] + p[9 + 2*pt];
        px = fminf(fmaxf(px, 0.f), (float)(W - 1));
        py = fminf(fmaxf(py, 0.f), (float)(H - 1));
        float xf = floorf(px), yf = floorf(py);
        float fx = px - xf, fy = py - yf;
        int x0 = (int)xf, y0 = (int)yf;
        int x1i = min(x0 + 1, W - 1), y1i = min(y0 + 1, H - 1);
        int ch = pt*NCLS + cls;
        float v00 = cm[(size_t)(y0*W  + x0 )*CLSC + ch];
        float v01 = cm[(size_t)(y0*W  + x1i)*CLSC + ch];
        float v10 = cm[(size_t)(y1i*W + x0 )*CLSC + ch];
        float v11 = cm[(size_t)(y1i*W + x1i)*CLSC + ch];
        acc += v00*(1.f-fx)*(1.f-fy) + v01*fx*(1.f-fy)
             + v10*(1.f-fx)*fy       + v11*fx*fy;
    }
    out[((size_t)(n*NCLS + cls))*HW + rem] = acc;
}

// ---------------- launch ----------------
extern "C" void kernel_launch(void* const* d_in, const int* in_sizes, int n_in,
                              void* d_out, int out_size)
{
    (void)in_sizes; (void)n_in; (void)out_size;
    const float* reg_feat0 = (const float*)d_in[0];
    const float* reg_feat1 = (const float*)d_in[1];
    const float* cls_feat0 = (const float*)d_in[2];
    const float* cls_feat1 = (const float*)d_in[3];
    const float* anchor0   = (const float*)d_in[4];
    const float* anchor1   = (const float*)d_in[5];
    const float* dyn_w     = (const float*)d_in[6];
    const float* dyn_b     = (const float*)d_in[7];
    const float* reg_w     = (const float*)d_in[8];
    const float* cls_w     = (const float*)d_in[9];
    const float* cls_b     = (const float*)d_in[10];
    float* out = (float*)d_out;

    prep_dyn_kernel<<<(DYNC*CIN*9 + 255)/256, 256>>>(dyn_w);
    prep_cls_kernel<<<(CLSC*CIN + 255)/256, 256>>>(cls_w);

    dim3 blkA(32, 8);
    dyn_conv_kernel<<<dim3((W0c+31)/32, (H0c+7)/8, NB), blkA>>>(
        reg_feat0, reg_w, dyn_b, H0c, W0c, 0, 0);
    dyn_conv_kernel<<<dim3((W1c+31)/32, (H1c+7)/8, NB), blkA>>>(
        reg_feat1, reg_w, dyn_b, H1c, W1c, PRED_OFF1, REG_OFF1);

    cls_gemm_kernel<<<dim3((HW0+127)/128, (CLSC+63)/64, NB), 256>>>(
        cls_feat0, HW0, 0);
    cls_gemm_kernel<<<dim3((HW1+127)/128, (CLSC+63)/64, NB), 256>>>(
        cls_feat1, HW1, CLS_OFF1);

    geom_kernel<<<(NB*HW0 + 255)/256, 256>>>(
        anchor0, H0c, W0c, 0, 0, 0, out + O_CO0, out + O_RB0);
    geom_kernel<<<(NB*HW1 + 255)/256, 256>>>(
        anchor1, H1c, W1c, PRED_OFF1, REG_OFF1, 1, out + O_CO1, out + O_RB1);

    cls_sample_kernel<<<NB*HW0, NCLS>>>(
        out + O_CO0, cls_b, H0c, W0c, 0, (size_t)0, out + O_CLS0);
    cls_sample_kernel<<<NB*HW1, NCLS>>>(
        out + O_CO1, cls_b, H1c, W1c, PRED_OFF1, CLS_OFF1, out + O_CLS1);
}

// round 2
// speedup vs baseline: 1.8690x; 1.8690x over previous
#include <cuda_runtime.h>
#include <cstdint>

#define H0c 100
#define W0c 152
#define H1c 50
#define W1c 76
#define HW0 (H0c*W0c)          // 15200
#define HW1 (H1c*W1c)          // 3800
#define NB 2
#define CIN 256
#define DYNC 34
#define CLSC 720
#define NCLS 80
#define NPIX (NB*(HW0+HW1))    // 38000

// padded dims (rounded up to tile grid + 2)
#define HP0 114   // 7 tiles * 16 + 2
#define WP0 162   // 5 tiles * 32 + 2
#define HP1 66    // 4 tiles * 16 + 2
#define WP1 98    // 3 tiles * 32 + 2

// level-1 offsets into scratch
#define PRED_OFF1 (NB*HW0*DYNC)
#define REG_OFF1  (NB*HW0*4)
#define CLS_OFF1  ((size_t)NB*HW0*CLSC)

// output offsets (floats)
#define O_CLS0 0
#define O_CLS1 (NB*NCLS*HW0)
#define O_CO0  (O_CLS1 + NB*NCLS*HW1)
#define O_CO1  (O_CO0 + NB*4*HW0)
#define O_RB0  (O_CO1 + NB*4*HW1)
#define O_RB1  (O_RB0 + NB*4*HW0)

// ---------------- scratch (device globals; no runtime alloc) ----------------
__device__ float g_pred[NB*(HW0+HW1)*DYNC];           // [gpix][34]
__device__ float g_regmap[NB*(HW0+HW1)*4];            // [gpix][4]
__device__ float g_clsmap[(size_t)NB*(HW0+HW1)*CLSC]; // [pix][720]
__device__ __align__(16) float g_wAll[CIN*416];       // [c][34*12 dyn | 4 reg | 4 pad]
__device__ float g_wclsT[CIN*CLSC];                   // [c][oc]
__device__ float g_pad0[NB*CIN*HP0*WP0];
__device__ float g_pad1[NB*CIN*HP1*WP1];
__device__ float g_part[4*38*NPIX];                   // [cg][out0..37][gpix]

// ---------------- cp.async helpers ----------------
__device__ __forceinline__ void cpa4(uint32_t d, const float* s) {
    asm volatile("cp.async.ca.shared.global [%0],[%1],4;\n" :: "r"(d), "l"(s));
}
__device__ __forceinline__ void cpa16(uint32_t d, const float* s) {
    asm volatile("cp.async.cg.shared.global [%0],[%1],16;\n" :: "r"(d), "l"(s));
}
#define CP_COMMIT() asm volatile("cp.async.commit_group;\n")
#define CP_WAIT1()  asm volatile("cp.async.wait_group 1;\n")

// ---------------- weight prep ----------------
__global__ void pack_dyn_kernel(const float* __restrict__ dyn_w,  // [34][256][9]
                                const float* __restrict__ reg_w)  // [4][256]
{
    int i = blockIdx.x*blockDim.x + threadIdx.x;
    if (i >= CIN*416) return;
    int c = i / 416;
    int rem = i - c*416;
    float v = 0.f;
    if (rem < 408) {
        int o = rem / 12, k = rem - o*12;
        if (k < 9) v = dyn_w[(o*CIN + c)*9 + k];
    } else if (rem < 412) {
        v = reg_w[(rem - 408)*CIN + c];
    }
    g_wAll[i] = v;
}

__global__ void prep_cls_kernel(const float* __restrict__ cls_w) {
    int i = blockIdx.x*blockDim.x + threadIdx.x;
    if (i < CLSC*CIN) {
        int oc = i / CIN;
        int c  = i - oc*CIN;
        g_wclsT[c*CLSC + oc] = cls_w[i];
    }
}

// ---------------- zero-padded input copy ----------------
__global__ void pad_kernel(const float* __restrict__ in, int lvl,
                           int H, int W, int HP, int WP)
{
    float* out = lvl ? g_pad1 : g_pad0;
    int idx = blockIdx.x*blockDim.x + threadIdx.x;
    int total = NB*CIN*HP*WP;
    if (idx >= total) return;
    int px = idx % WP;
    int t  = idx / WP;
    int py = t % HP;
    int nc = t / HP;
    int x = px - 1, y = py - 1;
    out[idx] = (x >= 0 && x < W && y >= 0 && y < H)
               ? in[(size_t)nc*H*W + y*W + x] : 0.f;
}

// ---------------- fused 3x3 dyn conv + 1x1 reg conv ----------------
// grid (47, NB, 4); block (32,8); each thread owns 2 pixels (y, y+8)
// bx<35 -> level0 tile (5x7); else level1 tile (3x4). Channel group = blockIdx.z (64 ch).
__global__ void __launch_bounds__(256, 2) dyn_conv_kernel(
    const float* __restrict__ in0_unused)   // inputs come from g_pad*
{
    __shared__ float tileS[2][612];                 // 18 x 34
    __shared__ __align__(16) float wsS[2][416];

    int tx = threadIdx.x, ty = threadIdx.y;
    int tid = ty*32 + tx;
    int bx = blockIdx.x;
    int n  = blockIdx.y;
    int cg = blockIdx.z;

    int lvl = (bx >= 35);
    int H, W, WP, chStride, gx0, gy0, gbase;
    const float* pad;
    if (!lvl) {
        int tX = bx % 5, tY = bx / 5;
        H = H0c; W = W0c; WP = WP0; chStride = HP0*WP0;
        gx0 = tX*32; gy0 = tY*16;
        pad = g_pad0; gbase = n*HW0;
    } else {
        int b = bx - 35;
        int tX = b % 3, tY = b / 3;
        H = H1c; W = W1c; WP = WP1; chStride = HP1*WP1;
        gx0 = tX*32; gy0 = tY*16;
        pad = g_pad1; gbase = NB*HW0 + n*HW1;
    }
    const float* padC = pad + ((size_t)(n*CIN + cg*64))*chStride + gy0*WP + gx0;
    const float* wsrc = g_wAll + (cg*64)*416;

    uint32_t tileB = (uint32_t)__cvta_generic_to_shared(&tileS[0][0]);
    uint32_t wsB   = (uint32_t)__cvta_generic_to_shared(&wsS[0][0]);

    float acc0[DYNC], acc1[DYNC];
    #pragma unroll
    for (int o = 0; o < DYNC; o++) { acc0[o] = 0.f; acc1[o] = 0.f; }
    float r00=0.f, r01=0.f, r02=0.f, r03=0.f;
    float r10=0.f, r11=0.f, r12=0.f, r13=0.f;

    // preload channel 0 into stage 0
    {
        const float* src = padC;
        for (int idx = tid; idx < 612; idx += 256) {
            int r = idx / 34, cc = idx - r*34;
            cpa4(tileB + idx*4, src + r*WP + cc);
        }
        if (tid < 104) cpa16(wsB + tid*16, wsrc + tid*4);
    }
    CP_COMMIT();

    #pragma unroll 1
    for (int c = 0; c < 64; c++) {
        int cur = c & 1;
        if (c + 1 < 64) {
            int nxt = cur ^ 1;
            const float* src = padC + (c+1)*chStride;
            for (int idx = tid; idx < 612; idx += 256) {
                int r = idx / 34, cc = idx - r*34;
                cpa4(tileB + (nxt*612 + idx)*4, src + r*WP + cc);
            }
            if (tid < 104) cpa16(wsB + nxt*1664 + tid*16, wsrc + (c+1)*416 + tid*4);
        }
        CP_COMMIT();
        CP_WAIT1();
        __syncthreads();

        const float* T = tileS[cur];
        int b0 = ty*34 + tx;
        float v0[9], v1[9];
        #pragma unroll
        for (int dy = 0; dy < 3; dy++)
            #pragma unroll
            for (int dx = 0; dx < 3; dx++) {
                v0[dy*3+dx] = T[b0 + dy*34 + dx];
                v1[dy*3+dx] = T[b0 + (dy+8)*34 + dx];
            }

        const float4* Wv = (const float4*)wsS[cur];
        #pragma unroll
        for (int o = 0; o < DYNC; o++) {
            float4 wa = Wv[o*3+0];
            float4 wb = Wv[o*3+1];
            float4 wc = Wv[o*3+2];
            float a = acc0[o];
            a = fmaf(wa.x, v0[0], a); a = fmaf(wa.y, v0[1], a);
            a = fmaf(wa.z, v0[2], a); a = fmaf(wa.w, v0[3], a);
            a = fmaf(wb.x, v0[4], a); a = fmaf(wb.y, v0[5], a);
            a = fmaf(wb.z, v0[6], a); a = fmaf(wb.w, v0[7], a);
            a = fmaf(wc.x, v0[8], a);
            acc0[o] = a;
            float b2 = acc1[o];
            b2 = fmaf(wa.x, v1[0], b2); b2 = fmaf(wa.y, v1[1], b2);
            b2 = fmaf(wa.z, v1[2], b2); b2 = fmaf(wa.w, v1[3], b2);
            b2 = fmaf(wb.x, v1[4], b2); b2 = fmaf(wb.y, v1[5], b2);
            b2 = fmaf(wb.z, v1[6], b2); b2 = fmaf(wb.w, v1[7], b2);
            b2 = fmaf(wc.x, v1[8], b2);
            acc1[o] = b2;
        }
        float4 wr = Wv[102];
        r00 = fmaf(wr.x, v0[4], r00); r01 = fmaf(wr.y, v0[4], r01);
        r02 = fmaf(wr.z, v0[4], r02); r03 = fmaf(wr.w, v0[4], r03);
        r10 = fmaf(wr.x, v1[4], r10); r11 = fmaf(wr.y, v1[4], r11);
        r12 = fmaf(wr.z, v1[4], r12); r13 = fmaf(wr.w, v1[4], r13);
        __syncthreads();
    }

    int x = gx0 + tx;
    int y0 = gy0 + ty;
    int partBase = cg*38*NPIX;
    if (x < W && y0 < H) {
        int gp = gbase + y0*W + x;
        #pragma unroll
        for (int o = 0; o < DYNC; o++)
            g_part[partBase + o*NPIX + gp] = acc0[o];
        g_part[partBase + 34*NPIX + gp] = r00;
        g_part[partBase + 35*NPIX + gp] = r01;
        g_part[partBase + 36*NPIX + gp] = r02;
        g_part[partBase + 37*NPIX + gp] = r03;
    }
    int y1 = y0 + 8;
    if (x < W && y1 < H) {
        int gp = gbase + y1*W + x;
        #pragma unroll
        for (int o = 0; o < DYNC; o++)
            g_part[partBase + o*NPIX + gp] = acc1[o];
        g_part[partBase + 34*NPIX + gp] = r10;
        g_part[partBase + 35*NPIX + gp] = r11;
        g_part[partBase + 36*NPIX + gp] = r12;
        g_part[partBase + 37*NPIX + gp] = r13;
    }
}

// ---------------- reduce partials -> g_pred (+bias) & g_regmap ----------------
__global__ void reduce_kernel(const float* __restrict__ dyn_b)
{
    int pix = blockIdx.x*blockDim.x + threadIdx.x;
    if (pix >= NPIX) return;
    #pragma unroll
    for (int o = 0; o < DYNC; o++) {
        float s = 0.f;
        #pragma unroll
        for (int cg = 0; cg < 4; cg++)
            s += g_part[(cg*38 + o)*NPIX + pix];
        g_pred[(size_t)pix*DYNC + o] = s + dyn_b[o];
    }
    float4 r = make_float4(0.f, 0.f, 0.f, 0.f);
    #pragma unroll
    for (int cg = 0; cg < 4; cg++) {
        r.x += g_part[(cg*38 + 34)*NPIX + pix];
        r.y += g_part[(cg*38 + 35)*NPIX + pix];
        r.z += g_part[(cg*38 + 36)*NPIX + pix];
        r.w += g_part[(cg*38 + 37)*NPIX + pix];
    }
    *(float4*)&g_regmap[(size_t)pix*4] = r;
}

// ---------------- cls 1x1 conv: GEMM 720x256 over pixels ----------------
__global__ void __launch_bounds__(256) cls_gemm_kernel(
    const float* __restrict__ in, int HW, size_t clsOff)
{
    __shared__ __align__(16) float As[16*128];
    __shared__ __align__(16) float Bs[16*64];

    int t = threadIdx.x;
    int txp = t & 15;
    int typ = t >> 4;
    int n = blockIdx.z;
    int pixbase = blockIdx.x*128;
    int ocbase  = blockIdx.y*64;

    const float* inN = in + (size_t)n*CIN*HW;

    float acc[8][4];
    #pragma unroll
    for (int i = 0; i < 8; i++)
        #pragma unroll
        for (int j = 0; j < 4; j++) acc[i][j] = 0.f;

    for (int kt = 0; kt < CIN; kt += 16) {
        #pragma unroll
        for (int i = 0; i < 8; i++) {
            int idx = t + i*256;
            int k = idx >> 7;
            int m = idx & 127;
            int pix = pixbase + m;
            As[idx] = (pix < HW) ? inN[(size_t)(kt + k)*HW + pix] : 0.f;
        }
        #pragma unroll
        for (int i = 0; i < 4; i++) {
            int idx = t + i*256;
            int k = idx >> 6;
            int oc = ocbase + (idx & 63);
            Bs[idx] = (oc < CLSC) ? g_wclsT[(kt + k)*CLSC + oc] : 0.f;
        }
        __syncthreads();

        #pragma unroll
        for (int k = 0; k < 16; k++) {
            float4 a0 = *(const float4*)&As[k*128 + txp*8];
            float4 a1 = *(const float4*)&As[k*128 + txp*8 + 4];
            float4 b  = *(const float4*)&Bs[k*64 + typ*4];
            float av[8] = {a0.x,a0.y,a0.z,a0.w,a1.x,a1.y,a1.z,a1.w};
            float bv[4] = {b.x,b.y,b.z,b.w};
            #pragma unroll
            for (int i = 0; i < 8; i++)
                #pragma unroll
                for (int j = 0; j < 4; j++)
                    acc[i][j] = fmaf(av[i], bv[j], acc[i][j]);
        }
        __syncthreads();
    }

    float* cm = g_clsmap + clsOff + (size_t)n*HW*CLSC;
    int oc = ocbase + typ*4;
    if (oc < CLSC) {
        #pragma unroll
        for (int i = 0; i < 8; i++) {
            int pix = pixbase + txp*8 + i;
            if (pix < HW) {
                *(float4*)&cm[(size_t)pix*CLSC + oc] =
                    make_float4(acc[i][0], acc[i][1], acc[i][2], acc[i][3]);
            }
        }
    }
}

// ---------------- geometry + reg sampling ----------------
__device__ __forceinline__ float bilin4(const float* __restrict__ rm,
                                        int H, int W, float px, float py, int ch)
{
    px = fminf(fmaxf(px, 0.f), (float)(W - 1));
    py = fminf(fmaxf(py, 0.f), (float)(H - 1));
    float xf = floorf(px), yf = floorf(py);
    float fx = px - xf, fy = py - yf;
    int x0 = (int)xf, y0 = (int)yf;
    int x1 = min(x0 + 1, W - 1), y1 = min(y0 + 1, H - 1);
    float v00 = rm[(y0*W + x0)*4 + ch];
    float v01 = rm[(y0*W + x1)*4 + ch];
    float v10 = rm[(y1*W + x0)*4 + ch];
    float v11 = rm[(y1*W + x1)*4 + ch];
    return v00*(1.f-fx)*(1.f-fy) + v01*fx*(1.f-fy)
         + v10*(1.f-fx)*fy       + v11*fx*fy;
}

__global__ void geom_kernel(const float* __restrict__ anchor,
                            int H, int W, int predOff, int regOff, int isL1,
                            float* __restrict__ out_coarse,
                            float* __restrict__ out_regbox)
{
    int t = blockIdx.x*blockDim.x + threadIdx.x;
    int HW = H*W;
    if (t >= NB*HW) return;
    int n = t / HW;
    int rem = t - n*HW;

    const float* p = g_pred + predOff + (size_t)t*DYNC;
    float x1b = anchor[(n*4 + 0)*HW + rem] + p[0];
    float y1b = anchor[(n*4 + 1)*HW + rem] + p[1];
    float x2b = anchor[(n*4 + 2)*HW + rem] + p[2];
    float y2b = anchor[(n*4 + 3)*HW + rem] + p[3];
    float cx = 0.5f*(x1b + x2b), cy = 0.5f*(y1b + y2b);
    float th_h = (y2b - y1b)*0.25f;
    float th_w = (x2b - x1b)*0.25f;
    float b0 = p[4], b1 = p[5], b2 = p[6], b3 = p[7];
    float bc0 = b0 - (fmaxf(b0 - th_h, 0.f) + fminf(b0 + th_h, 0.f));
    float bc1 = b1 - (fmaxf(b1 - th_w, 0.f) + fminf(b1 + th_w, 0.f));
    float bc2 = b2 - (fmaxf(b2 - th_h, 0.f) + fminf(b2 + th_h, 0.f));
    float bc3 = b3 - (fmaxf(b3 - th_w, 0.f) + fminf(b3 + th_w, 0.f));

    float ptx[4] = {x1b, cx + bc1, x2b, cx + bc3};
    float pty[4] = {cy + bc0, y1b, cy + bc2, y2b};

    const float* rm = g_regmap + regOff + (size_t)n*HW*4;
    float r[4];
    #pragma unroll
    for (int pc = 0; pc < 4; pc++)
        r[pc] = bilin4(rm, H, W, ptx[pc], pty[pc], pc);

    if (isL1) {
        const float* rml = g_regmap + (size_t)n*HW0*4;
        #pragma unroll
        for (int pc = 0; pc < 4; pc++) {
            float rl = 0.5f*bilin4(rml, H0c, W0c, 2.f*ptx[pc], 2.f*pty[pc], pc);
            float al = p[26 + 2*pc], ah = p[27 + 2*pc];
            float m = fmaxf(al, ah);
            float el = expf(al - m), eh = expf(ah - m);
            float inv = 1.f/(el + eh);
            r[pc] = (el*rl + eh*r[pc])*inv;
        }
    }

    out_coarse[(n*4 + 0)*HW + rem] = x1b;
    out_coarse[(n*4 + 1)*HW + rem] = y1b;
    out_coarse[(n*4 + 2)*HW + rem] = x2b;
    out_coarse[(n*4 + 3)*HW + rem] = y2b;
    out_regbox[(n*4 + 0)*HW + rem] = x1b + r[0];
    out_regbox[(n*4 + 1)*HW + rem] = y1b + r[1];
    out_regbox[(n*4 + 2)*HW + rem] = x2b + r[2];
    out_regbox[(n*4 + 3)*HW + rem] = y2b + r[3];
}

// ---------------- cls sampling ----------------
__global__ void cls_sample_kernel(const float* __restrict__ coarse,
                                  const float* __restrict__ cls_b,
                                  int H, int W, int predOff, size_t clsOff,
                                  float* __restrict__ out)
{
    int t = blockIdx.x;
    int HW = H*W;
    int n = t / HW;
    int rem = t - n*HW;

    const float* p = g_pred + predOff + (size_t)t*DYNC;
    float x1b = coarse[(n*4 + 0)*HW + rem];
    float y1b = coarse[(n*4 + 1)*HW + rem];
    float x2b = coarse[(n*4 + 2)*HW + rem];
    float y2b = coarse[(n*4 + 3)*HW + rem];
    float X[3] = {x1b, 0.5f*(x1b + x2b), x2b};
    float Y[3] = {y1b, 0.5f*(y1b + y2b), y2b};

    int cls = threadIdx.x;
    float acc = cls_b[cls];
    const float* cm = g_clsmap + clsOff + (size_t)n*HW*CLSC;

    #pragma unroll
    for (int pt = 0; pt < 9; pt++) {
        float px = X[pt/3] + p[8 + 2*pt];
        float py = Y[pt%3] + p[9 + 2*pt];
        px = fminf(fmaxf(px, 0.f), (float)(W - 1));
        py = fminf(fmaxf(py, 0.f), (float)(H - 1));
        float xf = floorf(px), yf = floorf(py);
        float fx = px - xf, fy = py - yf;
        int x0 = (int)xf, y0 = (int)yf;
        int x1i = min(x0 + 1, W - 1), y1i = min(y0 + 1, H - 1);
        int ch = pt*NCLS + cls;
        float v00 = cm[(size_t)(y0*W  + x0 )*CLSC + ch];
        float v01 = cm[(size_t)(y0*W  + x1i)*CLSC + ch];
        float v10 = cm[(size_t)(y1i*W + x0 )*CLSC + ch];
        float v11 = cm[(size_t)(y1i*W + x1i)*CLSC + ch];
        acc += v00*(1.f-fx)*(1.f-fy) + v01*fx*(1.f-fy)
             + v10*(1.f-fx)*fy       + v11*fx*fy;
    }
    out[((size_t)(n*NCLS + cls))*HW + rem] = acc;
}

// ---------------- launch ----------------
extern "C" void kernel_launch(void* const* d_in, const int* in_sizes, int n_in,
                              void* d_out, int out_size)
{
    (void)in_sizes; (void)n_in; (void)out_size;
    const float* reg_feat0 = (const float*)d_in[0];
    const float* reg_feat1 = (const float*)d_in[1];
    const float* cls_feat0 = (const float*)d_in[2];
    const float* cls_feat1 = (const float*)d_in[3];
    const float* anchor0   = (const float*)d_in[4];
    const float* anchor1   = (const float*)d_in[5];
    const float* dyn_w     = (const float*)d_in[6];
    const float* dyn_b     = (const float*)d_in[7];
    const float* reg_w     = (const float*)d_in[8];
    const float* cls_w     = (const float*)d_in[9];
    const float* cls_b     = (const float*)d_in[10];
    float* out = (float*)d_out;

    pack_dyn_kernel<<<(CIN*416 + 255)/256, 256>>>(dyn_w, reg_w);
    prep_cls_kernel<<<(CLSC*CIN + 255)/256, 256>>>(cls_w);

    pad_kernel<<<(NB*CIN*HP0*WP0 + 255)/256, 256>>>(reg_feat0, 0, H0c, W0c, HP0, WP0);
    pad_kernel<<<(NB*CIN*HP1*WP1 + 255)/256, 256>>>(reg_feat1, 1, H1c, W1c, HP1, WP1);

    dyn_conv_kernel<<<dim3(47, NB, 4), dim3(32, 8)>>>(nullptr);
    reduce_kernel<<<(NPIX + 255)/256, 256>>>(dyn_b);

    cls_gemm_kernel<<<dim3((HW0+127)/128, (CLSC+63)/64, NB), 256>>>(cls_feat0, HW0, 0);
    cls_gemm_kernel<<<dim3((HW1+127)/128, (CLSC+63)/64, NB), 256>>>(cls_feat1, HW1, CLS_OFF1);

    geom_kernel<<<(NB*HW0 + 255)/256, 256>>>(
        anchor0, H0c, W0c, 0, 0, 0, out + O_CO0, out + O_RB0);
    geom_kernel<<<(NB*HW1 + 255)/256, 256>>>(
        anchor1, H1c, W1c, PRED_OFF1, REG_OFF1, 1, out + O_CO1, out + O_RB1);

    cls_sample_kernel<<<NB*HW0, NCLS>>>(
        out + O_CO0, cls_b, H0c, W0c, 0, (size_t)0, out + O_CLS0);
    cls_sample_kernel<<<NB*HW1, NCLS>>>(
        out + O_CO1, cls_b, H1c, W1c, PRED_OFF1, CLS_OFF1, out + O_CLS1);
}

// round 5
// speedup vs baseline: 2.8723x; 1.5368x over previous
#include <cuda_runtime.h>
#include <cuda_bf16.h>
#include <cstdint>

#define H0c 100
#define W0c 152
#define H1c 50
#define W1c 76
#define HW0 (H0c*W0c)          // 15200
#define HW1 (H1c*W1c)          // 3800
#define NB 2
#define CIN 256
#define DYNC 34
#define CLSC 720
#define NCLS 80
#define NPIX (NB*(HW0+HW1))    // 38000
#define NPIXP 38016            // 297*128
#define KSPLIT 768             // 3*CIN
#define OCP 768                // padded oc

// padded dims
#define HP0 114
#define WP0 162
#define HP1 66
#define WP1 98

#define PRED_OFF1 (NB*HW0*DYNC)
#define REG_OFF1  (NB*HW0*4)
#define CLS_OFF1  ((size_t)NB*HW0*CLSC)

#define O_CLS0 0
#define O_CLS1 (NB*NCLS*HW0)
#define O_CO0  (O_CLS1 + NB*NCLS*HW1)
#define O_CO1  (O_CO0 + NB*4*HW0)
#define O_RB0  (O_CO1 + NB*4*HW1)
#define O_RB1  (O_RB0 + NB*4*HW0)

// ---------------- scratch ----------------
__device__ float g_pred[NB*(HW0+HW1)*DYNC];
__device__ float g_regmap[NB*(HW0+HW1)*4];
__device__ float g_clsmap[(size_t)NPIXP*CLSC];
__device__ __align__(16) float g_wAll[CIN*416];
__device__ float g_pad0[NB*CIN*HP0*WP0];
__device__ float g_pad1[NB*CIN*HP1*WP1];
__device__ float g_part[4*38*NPIX];
__device__ __align__(16) __nv_bfloat16 g_featS[(size_t)NPIXP*KSPLIT];  // [pix][768]
__device__ __align__(16) __nv_bfloat16 g_wclsS[(size_t)OCP*KSPLIT];   // [oc][768]

// ---------------- PTX helpers ----------------
__device__ __forceinline__ void cpa4(uint32_t d, const float* s) {
    asm volatile("cp.async.ca.shared.global [%0],[%1],4;\n" :: "r"(d), "l"(s));
}
__device__ __forceinline__ void cpa16(uint32_t d, const void* s) {
    asm volatile("cp.async.cg.shared.global [%0],[%1],16;\n" :: "r"(d), "l"(s));
}
#define CP_COMMIT() asm volatile("cp.async.commit_group;\n")
#define CP_WAIT1()  asm volatile("cp.async.wait_group 1;\n")
#define CP_WAIT0()  asm volatile("cp.async.wait_group 0;\n")

__device__ __forceinline__ void ldm_x4(uint32_t& r0, uint32_t& r1,
                                       uint32_t& r2, uint32_t& r3, uint32_t addr) {
    asm volatile("ldmatrix.sync.aligned.m8n8.x4.shared.b16 {%0,%1,%2,%3},[%4];"
                 : "=r"(r0), "=r"(r1), "=r"(r2), "=r"(r3) : "r"(addr));
}
__device__ __forceinline__ void mma_bf16(float* c, uint32_t a0, uint32_t a1,
                                         uint32_t a2, uint32_t a3,
                                         uint32_t b0, uint32_t b1) {
    asm volatile("mma.sync.aligned.m16n8k16.row.col.f32.bf16.bf16.f32 "
                 "{%0,%1,%2,%3},{%4,%5,%6,%7},{%8,%9},{%0,%1,%2,%3};"
                 : "+f"(c[0]), "+f"(c[1]), "+f"(c[2]), "+f"(c[3])
                 : "r"(a0), "r"(a1), "r"(a2), "r"(a3), "r"(b0), "r"(b1));
}

// ---------------- weight prep ----------------
__global__ void pack_dyn_kernel(const float* __restrict__ dyn_w,
                                const float* __restrict__ reg_w)
{
    int i = blockIdx.x*blockDim.x + threadIdx.x;
    if (i >= CIN*416) return;
    int c = i / 416;
    int rem = i - c*416;
    float v = 0.f;
    if (rem < 408) {
        int o = rem / 12, k = rem - o*12;
        if (k < 9) v = dyn_w[(o*CIN + c)*9 + k];
    } else if (rem < 412) {
        v = reg_w[(rem - 408)*CIN + c];
    }
    g_wAll[i] = v;
}

// cls weight split: B' = [Bhi | Bhi | Blo], rows padded to 768
__global__ void split_wcls_kernel(const float* __restrict__ cls_w) {
    int i = blockIdx.x*blockDim.x + threadIdx.x;
    if (i >= OCP*CIN) return;
    int oc = i >> 8, c = i & 255;
    size_t o = (size_t)oc*KSPLIT + c;
    if (oc < CLSC) {
        float v = cls_w[i];
        __nv_bfloat16 h = __float2bfloat16(v);
        __nv_bfloat16 l = __float2bfloat16(v - __bfloat162float(h));
        g_wclsS[o] = h;
        g_wclsS[o + 256] = h;
        g_wclsS[o + 512] = l;
    } else {
        __nv_bfloat16 z = __float2bfloat16(0.f);
        g_wclsS[o] = z; g_wclsS[o + 256] = z; g_wclsS[o + 512] = z;
    }
}

// feature transpose + split: in [N][256][HW] -> featS [gpix][768] = [Ahi|Alo|Ahi]
__global__ void split_feat_kernel(const float* __restrict__ in, int HW, int lvl)
{
    __shared__ float t[32][33];
    int tx = threadIdx.x, ty = threadIdx.y;
    int n = blockIdx.z;
    int chbase = blockIdx.y*32;
    int pixbase = blockIdx.x*32;
    int pix = pixbase + tx;
    #pragma unroll
    for (int j = 0; j < 4; j++) {
        int ch = ty + j*8;
        t[ch][tx] = (pix < HW) ? in[((size_t)(n*CIN + chbase + ch))*HW + pix] : 0.f;
    }
    __syncthreads();
    int base = lvl ? (NB*HW0 + n*HW1) : (n*HW0);
    #pragma unroll
    for (int j = 0; j < 4; j++) {
        int pr = ty + j*8;
        int opix = pixbase + pr;
        if (opix < HW) {
            float v = t[tx][pr];
            __nv_bfloat16 h = __float2bfloat16(v);
            __nv_bfloat16 l = __float2bfloat16(v - __bfloat162float(h));
            size_t o = (size_t)(base + opix)*KSPLIT + chbase + tx;
            g_featS[o] = h;
            g_featS[o + 256] = l;
            g_featS[o + 512] = h;
        }
    }
}

__global__ void zero_pad_feat_kernel() {
    int i = blockIdx.x*blockDim.x + threadIdx.x;
    if (i < (NPIXP - NPIX)*KSPLIT)
        g_featS[(size_t)NPIX*KSPLIT + i] = __float2bfloat16(0.f);
}

// ---------------- padded input copy ----------------
__global__ void pad_kernel(const float* __restrict__ in, int lvl,
                           int H, int W, int HP, int WP)
{
    float* out = lvl ? g_pad1 : g_pad0;
    int idx = blockIdx.x*blockDim.x + threadIdx.x;
    int total = NB*CIN*HP*WP;
    if (idx >= total) return;
    int px = idx % WP;
    int t  = idx / WP;
    int py = t % HP;
    int nc = t / HP;
    int x = px - 1, y = py - 1;
    out[idx] = (x >= 0 && x < W && y >= 0 && y < H)
               ? in[(size_t)nc*H*W + y*W + x] : 0.f;
}

// ---------------- fused 3x3 dyn conv + 1x1 reg conv (fp32) ----------------
__global__ void __launch_bounds__(256, 2) dyn_conv_kernel(const float* __restrict__ unused)
{
    __shared__ float tileS[2][612];
    __shared__ __align__(16) float wsS[2][416];

    int tx = threadIdx.x, ty = threadIdx.y;
    int tid = ty*32 + tx;
    int bx = blockIdx.x;
    int n  = blockIdx.y;
    int cg = blockIdx.z;

    int lvl = (bx >= 35);
    int H, W, WP, chStride, gx0, gy0, gbase;
    const float* pad;
    if (!lvl) {
        int tX = bx % 5, tY = bx / 5;
        H = H0c; W = W0c; WP = WP0; chStride = HP0*WP0;
        gx0 = tX*32; gy0 = tY*16;
        pad = g_pad0; gbase = n*HW0;
    } else {
        int b = bx - 35;
        int tX = b % 3, tY = b / 3;
        H = H1c; W = W1c; WP = WP1; chStride = HP1*WP1;
        gx0 = tX*32; gy0 = tY*16;
        pad = g_pad1; gbase = NB*HW0 + n*HW1;
    }
    const float* padC = pad + ((size_t)(n*CIN + cg*64))*chStride + gy0*WP + gx0;
    const float* wsrc = g_wAll + (cg*64)*416;

    uint32_t tileB = (uint32_t)__cvta_generic_to_shared(&tileS[0][0]);
    uint32_t wsB   = (uint32_t)__cvta_generic_to_shared(&wsS[0][0]);

    float acc0[DYNC], acc1[DYNC];
    #pragma unroll
    for (int o = 0; o < DYNC; o++) { acc0[o] = 0.f; acc1[o] = 0.f; }
    float r00=0.f, r01=0.f, r02=0.f, r03=0.f;
    float r10=0.f, r11=0.f, r12=0.f, r13=0.f;

    {
        const float* src = padC;
        for (int idx = tid; idx < 612; idx += 256) {
            int r = idx / 34, cc = idx - r*34;
            cpa4(tileB + idx*4, src + r*WP + cc);
        }
        if (tid < 104) cpa16(wsB + tid*16, wsrc + tid*4);
    }
    CP_COMMIT();

    #pragma unroll 1
    for (int c = 0; c < 64; c++) {
        int cur = c & 1;
        if (c + 1 < 64) {
            int nxt = cur ^ 1;
            const float* src = padC + (c+1)*chStride;
            for (int idx = tid; idx < 612; idx += 256) {
                int r = idx / 34, cc = idx - r*34;
                cpa4(tileB + (nxt*612 + idx)*4, src + r*WP + cc);
            }
            if (tid < 104) cpa16(wsB + nxt*1664 + tid*16, wsrc + (c+1)*416 + tid*4);
        }
        CP_COMMIT();
        CP_WAIT1();
        __syncthreads();

        const float* T = tileS[cur];
        int b0 = ty*34 + tx;
        float v0[9], v1[9];
        #pragma unroll
        for (int dy = 0; dy < 3; dy++)
            #pragma unroll
            for (int dx = 0; dx < 3; dx++) {
                v0[dy*3+dx] = T[b0 + dy*34 + dx];
                v1[dy*3+dx] = T[b0 + (dy+8)*34 + dx];
            }

        const float4* Wv = (const float4*)wsS[cur];
        #pragma unroll
        for (int o = 0; o < DYNC; o++) {
            float4 wa = Wv[o*3+0];
            float4 wb = Wv[o*3+1];
            float4 wc = Wv[o*3+2];
            float a = acc0[o];
            a = fmaf(wa.x, v0[0], a); a = fmaf(wa.y, v0[1], a);
            a = fmaf(wa.z, v0[2], a); a = fmaf(wa.w, v0[3], a);
            a = fmaf(wb.x, v0[4], a); a = fmaf(wb.y, v0[5], a);
            a = fmaf(wb.z, v0[6], a); a = fmaf(wb.w, v0[7], a);
            a = fmaf(wc.x, v0[8], a);
            acc0[o] = a;
            float b2 = acc1[o];
            b2 = fmaf(wa.x, v1[0], b2); b2 = fmaf(wa.y, v1[1], b2);
            b2 = fmaf(wa.z, v1[2], b2); b2 = fmaf(wa.w, v1[3], b2);
            b2 = fmaf(wb.x, v1[4], b2); b2 = fmaf(wb.y, v1[5], b2);
            b2 = fmaf(wb.z, v1[6], b2); b2 = fmaf(wb.w, v1[7], b2);
            b2 = fmaf(wc.x, v1[8], b2);
            acc1[o] = b2;
        }
        float4 wr = Wv[102];
        r00 = fmaf(wr.x, v0[4], r00); r01 = fmaf(wr.y, v0[4], r01);
        r02 = fmaf(wr.z, v0[4], r02); r03 = fmaf(wr.w, v0[4], r03);
        r10 = fmaf(wr.x, v1[4], r10); r11 = fmaf(wr.y, v1[4], r11);
        r12 = fmaf(wr.z, v1[4], r12); r13 = fmaf(wr.w, v1[4], r13);
        __syncthreads();
    }

    int x = gx0 + tx;
    int y0 = gy0 + ty;
    int partBase = cg*38*NPIX;
    if (x < W && y0 < H) {
        int gp = gbase + y0*W + x;
        #pragma unroll
        for (int o = 0; o < DYNC; o++)
            g_part[partBase + o*NPIX + gp] = acc0[o];
        g_part[partBase + 34*NPIX + gp] = r00;
        g_part[partBase + 35*NPIX + gp] = r01;
        g_part[partBase + 36*NPIX + gp] = r02;
        g_part[partBase + 37*NPIX + gp] = r03;
    }
    int y1 = y0 + 8;
    if (x < W && y1 < H) {
        int gp = gbase + y1*W + x;
        #pragma unroll
        for (int o = 0; o < DYNC; o++)
            g_part[partBase + o*NPIX + gp] = acc1[o];
        g_part[partBase + 34*NPIX + gp] = r10;
        g_part[partBase + 35*NPIX + gp] = r11;
        g_part[partBase + 36*NPIX + gp] = r12;
        g_part[partBase + 37*NPIX + gp] = r13;
    }
}

// ---------------- reduce partials ----------------
__global__ void reduce_kernel(const float* __restrict__ dyn_b)
{
    int pix = blockIdx.x*blockDim.x + threadIdx.x;
    if (pix >= NPIX) return;
    #pragma unroll
    for (int o = 0; o < DYNC; o++) {
        float s = 0.f;
        #pragma unroll
        for (int cg = 0; cg < 4; cg++)
            s += g_part[(cg*38 + o)*NPIX + pix];
        g_pred[(size_t)pix*DYNC + o] = s + dyn_b[o];
    }
    float4 r = make_float4(0.f, 0.f, 0.f, 0.f);
    #pragma unroll
    for (int cg = 0; cg < 4; cg++) {
        r.x += g_part[(cg*38 + 34)*NPIX + pix];
        r.y += g_part[(cg*38 + 35)*NPIX + pix];
        r.z += g_part[(cg*38 + 36)*NPIX + pix];
        r.w += g_part[(cg*38 + 37)*NPIX + pix];
    }
    *(float4*)&g_regmap[(size_t)pix*4] = r;
}

// ---------------- cls GEMM via mma.sync bf16 ----------------
// D[38016][768] = featS[38016][768] x wclsS[768][768]^T
// BM=128, BN=128, BK=32; 256 threads = 8 warps (2 M x 4 N), warp tile 64x32
#define GSTR 40                 // smem row stride in bf16 elems (80 B)
#define STG_BYTES (128*GSTR*2)  // 10240 B per stage

__global__ void __launch_bounds__(256) cls_mma_kernel()
{
    __shared__ __align__(16) __nv_bfloat16 As[2][128*GSTR];
    __shared__ __align__(16) __nv_bfloat16 Bs[2][128*GSTR];

    int tid = threadIdx.x;
    int lane = tid & 31, wid = tid >> 5;
    int wm = wid & 1, wn = wid >> 1;
    int pixbase = blockIdx.x*128;
    int ocbase  = blockIdx.y*128;

    const __nv_bfloat16* Ag = g_featS + (size_t)pixbase*KSPLIT;
    const __nv_bfloat16* Bg = g_wclsS + (size_t)ocbase*KSPLIT;

    uint32_t AsB = (uint32_t)__cvta_generic_to_shared(&As[0][0]);
    uint32_t BsB = (uint32_t)__cvta_generic_to_shared(&Bs[0][0]);

    float acc[4][4][4];
    #pragma unroll
    for (int f = 0; f < 4; f++)
        #pragma unroll
        for (int j = 0; j < 4; j++)
            #pragma unroll
            for (int e = 0; e < 4; e++) acc[f][j][e] = 0.f;

    // stage load lambda-ish via macro: q in {tid, tid+256} covers 512 16B-chunks each matrix
    #define LOAD_STAGE(s, k0) do { \
        int q0 = tid, q1 = tid + 256; \
        int r0_ = q0 >> 2, c0_ = q0 & 3; \
        int r1_ = q1 >> 2, c1_ = q1 & 3; \
        cpa16(AsB + (s)*STG_BYTES + (uint32_t)(r0_*80 + c0_*16), Ag + (size_t)r0_*KSPLIT + (k0) + c0_*8); \
        cpa16(AsB + (s)*STG_BYTES + (uint32_t)(r1_*80 + c1_*16), Ag + (size_t)r1_*KSPLIT + (k0) + c1_*8); \
        cpa16(BsB + (s)*STG_BYTES + (uint32_t)(r0_*80 + c0_*16), Bg + (size_t)r0_*KSPLIT + (k0) + c0_*8); \
        cpa16(BsB + (s)*STG_BYTES + (uint32_t)(r1_*80 + c1_*16), Bg + (size_t)r1_*KSPLIT + (k0) + c1_*8); \
    } while (0)

    LOAD_STAGE(0, 0);
    CP_COMMIT();

    #pragma unroll 1
    for (int bk = 0; bk < 24; bk++) {
        int cur = bk & 1;
        if (bk < 23) {
            LOAD_STAGE(cur ^ 1, (bk + 1)*32);
            CP_COMMIT();
            CP_WAIT1();
        } else {
            CP_WAIT0();
        }
        __syncthreads();

        uint32_t abase = AsB + cur*STG_BYTES + (uint32_t)((wm*64 + (lane & 15))*80);
        uint32_t bbase = BsB + cur*STG_BYTES + (uint32_t)((wn*32 + (lane & 15))*80);
        uint32_t cofs0 = (uint32_t)(((lane >> 4)*8)*2);

        #pragma unroll
        for (int kk = 0; kk < 2; kk++) {
            uint32_t co = cofs0 + kk*32;
            uint32_t a[4][4];
            #pragma unroll
            for (int f = 0; f < 4; f++)
                ldm_x4(a[f][0], a[f][1], a[f][2], a[f][3], abase + f*16*80 + co);
            uint32_t b[2][4];
            #pragma unroll
            for (int g = 0; g < 2; g++)
                ldm_x4(b[g][0], b[g][1], b[g][2], b[g][3], bbase + g*16*80 + co);
            #pragma unroll
            for (int f = 0; f < 4; f++) {
                #pragma unroll
                for (int g = 0; g < 2; g++) {
                    mma_bf16(acc[f][2*g],   a[f][0], a[f][1], a[f][2], a[f][3],
                             b[g][0], b[g][2]);
                    mma_bf16(acc[f][2*g+1], a[f][0], a[f][1], a[f][2], a[f][3],
                             b[g][1], b[g][3]);
                }
            }
        }
        __syncthreads();
    }

    // epilogue: frag (m16n8): c0,c1 -> (row, col..col+1), c2,c3 -> (row+8, ...)
    int rowin = lane >> 2;
    int colin = (lane & 3)*2;
    #pragma unroll
    for (int f = 0; f < 4; f++) {
        int pix = pixbase + wm*64 + f*16 + rowin;
        #pragma unroll
        for (int j = 0; j < 4; j++) {
            int oc = ocbase + wn*32 + j*8 + colin;
            if (oc < CLSC) {
                float* d0 = g_clsmap + (size_t)pix*CLSC + oc;
                d0[0] = acc[f][j][0];
                d0[1] = acc[f][j][1];
                float* d1 = g_clsmap + (size_t)(pix + 8)*CLSC + oc;
                d1[0] = acc[f][j][2];
                d1[1] = acc[f][j][3];
            }
        }
    }
}

// ---------------- geometry + reg sampling ----------------
__device__ __forceinline__ float bilin4(const float* __restrict__ rm,
                                        int H, int W, float px, float py, int chn)
{
    px = fminf(fmaxf(px, 0.f), (float)(W - 1));
    py = fminf(fmaxf(py, 0.f), (float)(H - 1));
    float xf = floorf(px), yf = floorf(py);
    float fx = px - xf, fy = py - yf;
    int x0 = (int)xf, y0 = (int)yf;
    int x1 = min(x0 + 1, W - 1), y1 = min(y0 + 1, H - 1);
    float v00 = rm[(y0*W + x0)*4 + chn];
    float v01 = rm[(y0*W + x1)*4 + chn];
    float v10 = rm[(y1*W + x0)*4 + chn];
    float v11 = rm[(y1*W + x1)*4 + chn];
    return v00*(1.f-fx)*(1.f-fy) + v01*fx*(1.f-fy)
         + v10*(1.f-fx)*fy       + v11*fx*fy;
}

__global__ void geom_kernel(const float* __restrict__ anchor,
                            int H, int W, int predOff, int regOff, int isL1,
                            float* __restrict__ out_coarse,
                            float* __restrict__ out_regbox)
{
    int t = blockIdx.x*blockDim.x + threadIdx.x;
    int HW = H*W;
    if (t >= NB*HW) return;
    int n = t / HW;
    int rem = t - n*HW;

    const float* p = g_pred + predOff + (size_t)t*DYNC;
    float x1b = anchor[(n*4 + 0)*HW + rem] + p[0];
    float y1b = anchor[(n*4 + 1)*HW + rem] + p[1];
    float x2b = anchor[(n*4 + 2)*HW + rem] + p[2];
    float y2b = anchor[(n*4 + 3)*HW + rem] + p[3];
    float cx = 0.5f*(x1b + x2b), cy = 0.5f*(y1b + y2b);
    float th_h = (y2b - y1b)*0.25f;
    float th_w = (x2b - x1b)*0.25f;
    float b0 = p[4], b1 = p[5], b2 = p[6], b3 = p[7];
    float bc0 = b0 - (fmaxf(b0 - th_h, 0.f) + fminf(b0 + th_h, 0.f));
    float bc1 = b1 - (fmaxf(b1 - th_w, 0.f) + fminf(b1 + th_w, 0.f));
    float bc2 = b2 - (fmaxf(b2 - th_h, 0.f) + fminf(b2 + th_h, 0.f));
    float bc3 = b3 - (fmaxf(b3 - th_w, 0.f) + fminf(b3 + th_w, 0.f));

    float ptx[4] = {x1b, cx + bc1, x2b, cx + bc3};
    float pty[4] = {cy + bc0, y1b, cy + bc2, y2b};

    const float* rm = g_regmap + regOff + (size_t)n*HW*4;
    float r[4];
    #pragma unroll
    for (int pc = 0; pc < 4; pc++)
        r[pc] = bilin4(rm, H, W, ptx[pc], pty[pc], pc);

    if (isL1) {
        const float* rml = g_regmap + (size_t)n*HW0*4;
        #pragma unroll
        for (int pc = 0; pc < 4; pc++) {
            float rl = 0.5f*bilin4(rml, H0c, W0c, 2.f*ptx[pc], 2.f*pty[pc], pc);
            float al = p[26 + 2*pc], ah = p[27 + 2*pc];
            float m = fmaxf(al, ah);
            float el = expf(al - m), eh = expf(ah - m);
            float inv = 1.f/(el + eh);
            r[pc] = (el*rl + eh*r[pc])*inv;
        }
    }

    out_coarse[(n*4 + 0)*HW + rem] = x1b;
    out_coarse[(n*4 + 1)*HW + rem] = y1b;
    out_coarse[(n*4 + 2)*HW + rem] = x2b;
    out_coarse[(n*4 + 3)*HW + rem] = y2b;
    out_regbox[(n*4 + 0)*HW + rem] = x1b + r[0];
    out_regbox[(n*4 + 1)*HW + rem] = y1b + r[1];
    out_regbox[(n*4 + 2)*HW + rem] = x2b + r[2];
    out_regbox[(n*4 + 3)*HW + rem] = y2b + r[3];
}

// ---------------- cls sampling ----------------
__global__ void cls_sample_kernel(const float* __restrict__ coarse,
                                  const float* __restrict__ cls_b,
                                  int H, int W, int predOff, size_t clsOff,
                                  float* __restrict__ out)
{
    int t = blockIdx.x;
    int HW = H*W;
    int n = t / HW;
    int rem = t - n*HW;

    const float* p = g_pred + predOff + (size_t)t*DYNC;
    float x1b = coarse[(n*4 + 0)*HW + rem];
    float y1b = coarse[(n*4 + 1)*HW + rem];
    float x2b = coarse[(n*4 + 2)*HW + rem];
    float y2b = coarse[(n*4 + 3)*HW + rem];
    float X[3] = {x1b, 0.5f*(x1b + x2b), x2b};
    float Y[3] = {y1b, 0.5f*(y1b + y2b), y2b};

    int cls = threadIdx.x;
    float acc = cls_b[cls];
    const float* cm = g_clsmap + clsOff + (size_t)n*HW*CLSC;

    #pragma unroll
    for (int pt = 0; pt < 9; pt++) {
        float px = X[pt/3] + p[8 + 2*pt];
        float py = Y[pt%3] + p[9 + 2*pt];
        px = fminf(fmaxf(px, 0.f), (float)(W - 1));
        py = fminf(fmaxf(py, 0.f), (float)(H - 1));
        float xf = floorf(px), yf = floorf(py);
        float fx = px - xf, fy = py - yf;
        int x0 = (int)xf, y0 = (int)yf;
        int x1i = min(x0 + 1, W - 1), y1i = min(y0 + 1, H - 1);
        int chn = pt*NCLS + cls;
        float v00 = cm[(size_t)(y0*W  + x0 )*CLSC + chn];
        float v01 = cm[(size_t)(y0*W  + x1i)*CLSC + chn];
        float v10 = cm[(size_t)(y1i*W + x0 )*CLSC + chn];
        float v11 = cm[(size_t)(y1i*W + x1i)*CLSC + chn];
        acc += v00*(1.f-fx)*(1.f-fy) + v01*fx*(1.f-fy)
             + v10*(1.f-fx)*fy       + v11*fx*fy;
    }
    out[((size_t)(n*NCLS + cls))*HW + rem] = acc;
}

// ---------------- launch ----------------
extern "C" void kernel_launch(void* const* d_in, const int* in_sizes, int n_in,
                              void* d_out, int out_size)
{
    (void)in_sizes; (void)n_in; (void)out_size;
    const float* reg_feat0 = (const float*)d_in[0];
    const float* reg_feat1 = (const float*)d_in[1];
    const float* cls_feat0 = (const float*)d_in[2];
    const float* cls_feat1 = (const float*)d_in[3];
    const float* anchor0   = (const float*)d_in[4];
    const float* anchor1   = (const float*)d_in[5];
    const float* dyn_w     = (const float*)d_in[6];
    const float* dyn_b     = (const float*)d_in[7];
    const float* reg_w     = (const float*)d_in[8];
    const float* cls_w     = (const float*)d_in[9];
    const float* cls_b     = (const float*)d_in[10];
    float* out = (float*)d_out;

    pack_dyn_kernel<<<(CIN*416 + 255)/256, 256>>>(dyn_w, reg_w);
    split_wcls_kernel<<<(OCP*CIN + 255)/256, 256>>>(cls_w);

    pad_kernel<<<(NB*CIN*HP0*WP0 + 255)/256, 256>>>(reg_feat0, 0, H0c, W0c, HP0, WP0);
    pad_kernel<<<(NB*CIN*HP1*WP1 + 255)/256, 256>>>(reg_feat1, 1, H1c, W1c, HP1, WP1);

    split_feat_kernel<<<dim3((HW0+31)/32, 8, NB), dim3(32,8)>>>(cls_feat0, HW0, 0);
    split_feat_kernel<<<dim3((HW1+31)/32, 8, NB), dim3(32,8)>>>(cls_feat1, HW1, 1);
    zero_pad_feat_kernel<<<((NPIXP-NPIX)*KSPLIT + 255)/256, 256>>>();

    dyn_conv_kernel<<<dim3(47, NB, 4), dim3(32, 8)>>>(nullptr);
    reduce_kernel<<<(NPIX + 255)/256, 256>>>(dyn_b);

    cls_mma_kernel<<<dim3(297, 6), 256>>>();

    geom_kernel<<<(NB*HW0 + 255)/256, 256>>>(
        anchor0, H0c, W0c, 0, 0, 0, out + O_CO0, out + O_RB0);
    geom_kernel<<<(NB*HW1 + 255)/256, 256>>>(
        anchor1, H1c, W1c, PRED_OFF1, REG_OFF1, 1, out + O_CO1, out + O_RB1);

    cls_sample_kernel<<<NB*HW0, NCLS>>>(
        out + O_CO0, cls_b, H0c, W0c, 0, (size_t)0, out + O_CLS0);
    cls_sample_kernel<<<NB*HW1, NCLS>>>(
        out + O_CO1, cls_b, H1c, W1c, PRED_OFF1, CLS_OFF1, out + O_CLS1);
}

// round 6
// speedup vs baseline: 3.1434x; 1.0944x over previous
#include <cuda_runtime.h>
#include <cuda_bf16.h>
#include <cstdint>

#define H0c 100
#define W0c 152
#define H1c 50
#define W1c 76
#define HW0 (H0c*W0c)          // 15200
#define HW1 (H1c*W1c)          // 3800
#define NB 2
#define CIN 256
#define DYNC 34
#define CLSC 720
#define NCLS 80
#define NPIX (NB*(HW0+HW1))    // 38000
#define NPIXP 38016            // 297*128
#define KSPLIT 768             // 3*CIN
#define OCP 768                // padded oc (cls)
#define KDYN 6912              // 9*768

// padded (H+2, W+2) dims for dyn GEMM A-matrix
#define PH0 102
#define PW0 154
#define PH1 52
#define PW1 78
#define PAD0TOT (NB*PH0*PW0)            // 31416
#define PADTOT (PAD0TOT + NB*PH1*PW1)   // 39528

#define PRED_OFF1 (NB*HW0*DYNC)
#define REG_OFF1  (NB*HW0*4)
#define CLS_OFF1  ((size_t)NB*HW0*CLSC)

#define O_CLS0 0
#define O_CLS1 (NB*NCLS*HW0)
#define O_CO0  (O_CLS1 + NB*NCLS*HW1)
#define O_CO1  (O_CO0 + NB*4*HW0)
#define O_RB0  (O_CO1 + NB*4*HW1)
#define O_RB1  (O_RB0 + NB*4*HW0)

// ---------------- scratch ----------------
__device__ float g_pred[NB*(HW0+HW1)*DYNC];
__device__ float g_regmap[NB*(HW0+HW1)*4];
__device__ float g_clsmap[(size_t)NPIXP*CLSC];
__device__ __align__(16) __nv_bfloat16 g_featS[(size_t)NPIXP*KSPLIT];  // cls A [pix][768]
__device__ __align__(16) __nv_bfloat16 g_wclsS[(size_t)OCP*KSPLIT];   // cls B [oc][768]
__device__ __align__(16) __nv_bfloat16 g_regS[(size_t)PADTOT*KSPLIT]; // dyn A [padpix][768]
__device__ __align__(16) __nv_bfloat16 g_wdynS[64*KDYN];              // dyn B [oc][9*768]

// ---------------- PTX helpers ----------------
__device__ __forceinline__ void cpa16(uint32_t d, const void* s) {
    asm volatile("cp.async.cg.shared.global [%0],[%1],16;\n" :: "r"(d), "l"(s));
}
#define CP_COMMIT() asm volatile("cp.async.commit_group;\n")
#define CP_WAIT1()  asm volatile("cp.async.wait_group 1;\n")
#define CP_WAIT0()  asm volatile("cp.async.wait_group 0;\n")

__device__ __forceinline__ void ldm_x4(uint32_t& r0, uint32_t& r1,
                                       uint32_t& r2, uint32_t& r3, uint32_t addr) {
    asm volatile("ldmatrix.sync.aligned.m8n8.x4.shared.b16 {%0,%1,%2,%3},[%4];"
                 : "=r"(r0), "=r"(r1), "=r"(r2), "=r"(r3) : "r"(addr));
}
__device__ __forceinline__ void mma_bf16(float* c, uint32_t a0, uint32_t a1,
                                         uint32_t a2, uint32_t a3,
                                         uint32_t b0, uint32_t b1) {
    asm volatile("mma.sync.aligned.m16n8k16.row.col.f32.bf16.bf16.f32 "
                 "{%0,%1,%2,%3},{%4,%5,%6,%7},{%8,%9},{%0,%1,%2,%3};"
                 : "+f"(c[0]), "+f"(c[1]), "+f"(c[2]), "+f"(c[3])
                 : "r"(a0), "r"(a1), "r"(a2), "r"(a3), "r"(b0), "r"(b1));
}

// ---------------- cls weight split: B' = [Bhi | Bhi | Blo] ----------------
__global__ void split_wcls_kernel(const float* __restrict__ cls_w) {
    int i = blockIdx.x*blockDim.x + threadIdx.x;
    if (i >= OCP*CIN) return;
    int oc = i >> 8, c = i & 255;
    size_t o = (size_t)oc*KSPLIT + c;
    if (oc < CLSC) {
        float v = cls_w[i];
        __nv_bfloat16 h = __float2bfloat16(v);
        __nv_bfloat16 l = __float2bfloat16(v - __bfloat162float(h));
        g_wclsS[o] = h;
        g_wclsS[o + 256] = h;
        g_wclsS[o + 512] = l;
    } else {
        __nv_bfloat16 z = __float2bfloat16(0.f);
        g_wclsS[o] = z; g_wclsS[o + 256] = z; g_wclsS[o + 512] = z;
    }
}

// dyn weight split: [64][9*768], per pos block [hi|hi|lo]
__global__ void split_wdyn_kernel(const float* __restrict__ dyn_w,
                                  const float* __restrict__ reg_w) {
    int i = blockIdx.x*blockDim.x + threadIdx.x;
    if (i >= 64*9*256) return;
    int oc = i / (9*256);
    int rem = i - oc*9*256;
    int p = rem >> 8, c = rem & 255;
    float v = 0.f;
    if (oc < DYNC) v = dyn_w[(oc*CIN + c)*9 + p];
    else if (oc < 38 && p == 4) v = reg_w[(oc - DYNC)*CIN + c];
    __nv_bfloat16 h = __float2bfloat16(v);
    __nv_bfloat16 l = __float2bfloat16(v - __bfloat162float(h));
    size_t o = (size_t)oc*KDYN + p*KSPLIT + c;
    g_wdynS[o] = h;
    g_wdynS[o + 256] = h;
    g_wdynS[o + 512] = l;
}

// cls feature transpose+split: [N][256][HW] -> featS [gpix][768] = [Ahi|Alo|Ahi]
__global__ void split_feat_kernel(const float* __restrict__ in, int HW, int lvl)
{
    __shared__ float t[32][33];
    int tx = threadIdx.x, ty = threadIdx.y;
    int n = blockIdx.z;
    int chbase = blockIdx.y*32;
    int pixbase = blockIdx.x*32;
    int pix = pixbase + tx;
    #pragma unroll
    for (int j = 0; j < 4; j++) {
        int ch = ty + j*8;
        t[ch][tx] = (pix < HW) ? in[((size_t)(n*CIN + chbase + ch))*HW + pix] : 0.f;
    }
    __syncthreads();
    int base = lvl ? (NB*HW0 + n*HW1) : (n*HW0);
    #pragma unroll
    for (int j = 0; j < 4; j++) {
        int pr = ty + j*8;
        int opix = pixbase + pr;
        if (opix < HW) {
            float v = t[tx][pr];
            __nv_bfloat16 h = __float2bfloat16(v);
            __nv_bfloat16 l = __float2bfloat16(v - __bfloat162float(h));
            size_t o = (size_t)(base + opix)*KSPLIT + chbase + tx;
            g_featS[o] = h;
            g_featS[o + 256] = l;
            g_featS[o + 512] = h;
        }
    }
}

__global__ void zero_pad_feat_kernel() {
    int i = blockIdx.x*blockDim.x + threadIdx.x;
    if (i < (NPIXP - NPIX)*KSPLIT)
        g_featS[(size_t)NPIX*KSPLIT + i] = __float2bfloat16(0.f);
}

// zero whole g_regS (borders stay zero after interior fill)
__global__ void zero_regS_kernel() {
    size_t i = (size_t)blockIdx.x*blockDim.x + threadIdx.x;
    size_t total = ((size_t)PADTOT*KSPLIT) / 8;  // uint4 granules
    if (i < total) ((uint4*)g_regS)[i] = make_uint4(0,0,0,0);
}

// reg feature transpose+split into PADDED pixel space: [padpix][768] = [hi|lo|hi]
__global__ void split_reg_kernel(const float* __restrict__ in, int HW, int lvl)
{
    __shared__ float t[32][33];
    int tx = threadIdx.x, ty = threadIdx.y;
    int n = blockIdx.z;
    int chbase = blockIdx.y*32;
    int pixbase = blockIdx.x*32;
    int pix = pixbase + tx;
    #pragma unroll
    for (int j = 0; j < 4; j++) {
        int ch = ty + j*8;
        t[ch][tx] = (pix < HW) ? in[((size_t)(n*CIN + chbase + ch))*HW + pix] : 0.f;
    }
    __syncthreads();
    int W = lvl ? W1c : W0c;
    int PW = lvl ? PW1 : PW0;
    int padBase = lvl ? (PAD0TOT + n*PH1*PW1) : (n*PH0*PW0);
    #pragma unroll
    for (int j = 0; j < 4; j++) {
        int pr = ty + j*8;
        int opix = pixbase + pr;
        if (opix < HW) {
            int y = opix / W, x = opix - y*W;
            float v = t[tx][pr];
            __nv_bfloat16 h = __float2bfloat16(v);
            __nv_bfloat16 l = __float2bfloat16(v - __bfloat162float(h));
            size_t o = (size_t)(padBase + (y+1)*PW + x + 1)*KSPLIT + chbase + tx;
            g_regS[o] = h;
            g_regS[o + 256] = l;
            g_regS[o + 512] = h;
        }
    }
}

// ---------------- dyn conv as implicit GEMM via mma.sync ----------------
// grid 330 tiles; BM=128 (8 rows x 16 cols of output), BN=64, K=9*768 in 216 chunks of 32
#define DSTR 40
#define DASTG (128*DSTR*2)   // 10240 B
#define DBSTG (64*DSTR*2)    // 5120 B

__global__ void __launch_bounds__(256) dyn_mma_kernel(const float* __restrict__ dyn_b)
{
    __shared__ __align__(16) __nv_bfloat16 As[2][128*DSTR];
    __shared__ __align__(16) __nv_bfloat16 Bs[2][64*DSTR];

    int tid = threadIdx.x;
    int lane = tid & 31, wid = tid >> 5;
    int wm = wid & 1, wn = wid >> 1;

    int bid = blockIdx.x;
    int lvl, n, tX, tY;
    if (bid < 260) { lvl = 0; n = bid/130; int t = bid - n*130; tY = t/10; tX = t - tY*10; }
    else { int b = bid - 260; lvl = 1; n = b/35; int t = b - n*35; tY = t/5; tX = t - tY*5; }
    int H  = lvl ? H1c : H0c;
    int W  = lvl ? W1c : W0c;
    int PW = lvl ? PW1 : PW0;
    int padBase = lvl ? (PAD0TOT + n*PH1*PW1) : (n*PH0*PW0);
    int gbase   = lvl ? (NB*HW0 + n*HW1) : (n*HW0);
    int y0 = tY*8, x0 = tX*16;

    // per-thread fixed rows for staging
    int rA0 = tid >> 2, cA = tid & 3;     // A rows rA0 and rA0+64
    int rB  = tid >> 2, cB = tid & 3;     // B row (oc)
    auto rowPix = [&](int r) {
        int y = y0 + (r >> 4); if (y >= H) y = H - 1;
        int x = x0 + (r & 15); if (x >= W) x = W - 1;
        return padBase + (y + 1)*PW + x + 1;
    };
    int aPix0 = rowPix(rA0);
    int aPix1 = rowPix(rA0 + 64);

    uint32_t AsB = (uint32_t)__cvta_generic_to_shared(&As[0][0]);
    uint32_t BsB = (uint32_t)__cvta_generic_to_shared(&Bs[0][0]);

    float acc[4][2][4];
    #pragma unroll
    for (int f = 0; f < 4; f++)
        #pragma unroll
        for (int j = 0; j < 2; j++)
            #pragma unroll
            for (int e = 0; e < 4; e++) acc[f][j][e] = 0.f;

    const __nv_bfloat16* Ag = g_regS;
    const __nv_bfloat16* Bg = g_wdynS + (size_t)rB*KDYN;

    #define DYN_LOAD(s, q) do { \
        int p_ = (q)/24, kc_ = (q) - p_*24; \
        int sh_ = (p_/3 - 1)*PW + (p_ - (p_/3)*3 - 1); \
        int ko_ = kc_*32 + cA*8; \
        cpa16(AsB + (s)*DASTG + (uint32_t)(rA0*80 + cA*16), \
              Ag + (size_t)(aPix0 + sh_)*KSPLIT + ko_); \
        cpa16(AsB + (s)*DASTG + (uint32_t)((rA0+64)*80 + cA*16), \
              Ag + (size_t)(aPix1 + sh_)*KSPLIT + ko_); \
        cpa16(BsB + (s)*DBSTG + (uint32_t)(rB*80 + cB*16), \
              Bg + (size_t)p_*KSPLIT + kc_*32 + cB*8); \
    } while (0)

    DYN_LOAD(0, 0);
    CP_COMMIT();

    #pragma unroll 1
    for (int q = 0; q < 216; q++) {
        int cur = q & 1;
        if (q < 215) {
            DYN_LOAD(cur ^ 1, q + 1);
            CP_COMMIT();
            CP_WAIT1();
        } else {
            CP_WAIT0();
        }
        __syncthreads();

        uint32_t abase = AsB + cur*DASTG + (uint32_t)((wm*64 + (lane & 15))*80);
        uint32_t bbase = BsB + cur*DBSTG + (uint32_t)((wn*16 + (lane & 15))*80);
        uint32_t cofs0 = (uint32_t)(((lane >> 4)*8)*2);

        #pragma unroll
        for (int kk = 0; kk < 2; kk++) {
            uint32_t co = cofs0 + kk*32;
            uint32_t a[4][4];
            #pragma unroll
            for (int f = 0; f < 4; f++)
                ldm_x4(a[f][0], a[f][1], a[f][2], a[f][3], abase + f*16*80 + co);
            uint32_t b[4];
            ldm_x4(b[0], b[1], b[2], b[3], bbase + co);
            #pragma unroll
            for (int f = 0; f < 4; f++) {
                mma_bf16(acc[f][0], a[f][0], a[f][1], a[f][2], a[f][3], b[0], b[2]);
                mma_bf16(acc[f][1], a[f][0], a[f][1], a[f][2], a[f][3], b[1], b[3]);
            }
        }
        __syncthreads();
    }

    // epilogue: scatter to g_pred (+bias) / g_regmap
    int rowin = lane >> 2;
    int colin = (lane & 3)*2;
    #pragma unroll
    for (int f = 0; f < 4; f++) {
        #pragma unroll
        for (int half = 0; half < 2; half++) {
            int tr = wm*64 + f*16 + rowin + half*8;
            int y = y0 + (tr >> 4), x = x0 + (tr & 15);
            if (y < H && x < W) {
                int gp = gbase + y*W + x;
                #pragma unroll
                for (int j = 0; j < 2; j++) {
                    int oc = wn*16 + j*8 + colin;
                    float v0 = acc[f][j][half*2];
                    float v1 = acc[f][j][half*2 + 1];
                    if (oc < DYNC) {
                        g_pred[(size_t)gp*DYNC + oc] = v0 + __ldg(dyn_b + oc);
                    } else if (oc < 38) {
                        g_regmap[(size_t)gp*4 + oc - DYNC] = v0;
                    }
                    int oc1 = oc + 1;
                    if (oc1 < DYNC) {
                        g_pred[(size_t)gp*DYNC + oc1] = v1 + __ldg(dyn_b + oc1);
                    } else if (oc1 < 38) {
                        g_regmap[(size_t)gp*4 + oc1 - DYNC] = v1;
                    }
                }
            }
        }
    }
}

// ---------------- cls GEMM via mma.sync bf16 ----------------
#define GSTR 40
#define STG_BYTES (128*GSTR*2)

__global__ void __launch_bounds__(256) cls_mma_kernel()
{
    __shared__ __align__(16) __nv_bfloat16 As[2][128*GSTR];
    __shared__ __align__(16) __nv_bfloat16 Bs[2][128*GSTR];

    int tid = threadIdx.x;
    int lane = tid & 31, wid = tid >> 5;
    int wm = wid & 1, wn = wid >> 1;
    int pixbase = blockIdx.x*128;
    int ocbase  = blockIdx.y*128;

    const __nv_bfloat16* Ag = g_featS + (size_t)pixbase*KSPLIT;
    const __nv_bfloat16* Bg = g_wclsS + (size_t)ocbase*KSPLIT;

    uint32_t AsB = (uint32_t)__cvta_generic_to_shared(&As[0][0]);
    uint32_t BsB = (uint32_t)__cvta_generic_to_shared(&Bs[0][0]);

    float acc[4][4][4];
    #pragma unroll
    for (int f = 0; f < 4; f++)
        #pragma unroll
        for (int j = 0; j < 4; j++)
            #pragma unroll
            for (int e = 0; e < 4; e++) acc[f][j][e] = 0.f;

    #define LOAD_STAGE(s, k0) do { \
        int q0 = tid, q1 = tid + 256; \
        int r0_ = q0 >> 2, c0_ = q0 & 3; \
        int r1_ = q1 >> 2, c1_ = q1 & 3; \
        cpa16(AsB + (s)*STG_BYTES + (uint32_t)(r0_*80 + c0_*16), Ag + (size_t)r0_*KSPLIT + (k0) + c0_*8); \
        cpa16(AsB + (s)*STG_BYTES + (uint32_t)(r1_*80 + c1_*16), Ag + (size_t)r1_*KSPLIT + (k0) + c1_*8); \
        cpa16(BsB + (s)*STG_BYTES + (uint32_t)(r0_*80 + c0_*16), Bg + (size_t)r0_*KSPLIT + (k0) + c0_*8); \
        cpa16(BsB + (s)*STG_BYTES + (uint32_t)(r1_*80 + c1_*16), Bg + (size_t)r1_*KSPLIT + (k0) + c1_*8); \
    } while (0)

    LOAD_STAGE(0, 0);
    CP_COMMIT();

    #pragma unroll 1
    for (int bk = 0; bk < 24; bk++) {
        int cur = bk & 1;
        if (bk < 23) {
            LOAD_STAGE(cur ^ 1, (bk + 1)*32);
            CP_COMMIT();
            CP_WAIT1();
        } else {
            CP_WAIT0();
        }
        __syncthreads();

        uint32_t abase = AsB + cur*STG_BYTES + (uint32_t)((wm*64 + (lane & 15))*80);
        uint32_t bbase = BsB + cur*STG_BYTES + (uint32_t)((wn*32 + (lane & 15))*80);
        uint32_t cofs0 = (uint32_t)(((lane >> 4)*8)*2);

        #pragma unroll
        for (int kk = 0; kk < 2; kk++) {
            uint32_t co = cofs0 + kk*32;
            uint32_t a[4][4];
            #pragma unroll
            for (int f = 0; f < 4; f++)
                ldm_x4(a[f][0], a[f][1], a[f][2], a[f][3], abase + f*16*80 + co);
            uint32_t b[2][4];
            #pragma unroll
            for (int g = 0; g < 2; g++)
                ldm_x4(b[g][0], b[g][1], b[g][2], b[g][3], bbase + g*16*80 + co);
            #pragma unroll
            for (int f = 0; f < 4; f++) {
                #pragma unroll
                for (int g = 0; g < 2; g++) {
                    mma_bf16(acc[f][2*g],   a[f][0], a[f][1], a[f][2], a[f][3],
                             b[g][0], b[g][2]);
                    mma_bf16(acc[f][2*g+1], a[f][0], a[f][1], a[f][2], a[f][3],
                             b[g][1], b[g][3]);
                }
            }
        }
        __syncthreads();
    }

    int rowin = lane >> 2;
    int colin = (lane & 3)*2;
    #pragma unroll
    for (int f = 0; f < 4; f++) {
        int pix = pixbase + wm*64 + f*16 + rowin;
        #pragma unroll
        for (int j = 0; j < 4; j++) {
            int oc = ocbase + wn*32 + j*8 + colin;
            if (oc < CLSC) {
                float* d0 = g_clsmap + (size_t)pix*CLSC + oc;
                d0[0] = acc[f][j][0];
                d0[1] = acc[f][j][1];
                float* d1 = g_clsmap + (size_t)(pix + 8)*CLSC + oc;
                d1[0] = acc[f][j][2];
                d1[1] = acc[f][j][3];
            }
        }
    }
}

// ---------------- geometry + reg sampling ----------------
__device__ __forceinline__ float bilin4(const float* __restrict__ rm,
                                        int H, int W, float px, float py, int chn)
{
    px = fminf(fmaxf(px, 0.f), (float)(W - 1));
    py = fminf(fmaxf(py, 0.f), (float)(H - 1));
    float xf = floorf(px), yf = floorf(py);
    float fx = px - xf, fy = py - yf;
    int x0 = (int)xf, y0 = (int)yf;
    int x1 = min(x0 + 1, W - 1), y1 = min(y0 + 1, H - 1);
    float v00 = rm[(y0*W + x0)*4 + chn];
    float v01 = rm[(y0*W + x1)*4 + chn];
    float v10 = rm[(y1*W + x0)*4 + chn];
    float v11 = rm[(y1*W + x1)*4 + chn];
    return v00*(1.f-fx)*(1.f-fy) + v01*fx*(1.f-fy)
         + v10*(1.f-fx)*fy       + v11*fx*fy;
}

__global__ void geom_kernel(const float* __restrict__ anchor,
                            int H, int W, int predOff, int regOff, int isL1,
                            float* __restrict__ out_coarse,
                            float* __restrict__ out_regbox)
{
    int t = blockIdx.x*blockDim.x + threadIdx.x;
    int HW = H*W;
    if (t >= NB*HW) return;
    int n = t / HW;
    int rem = t - n*HW;

    const float* p = g_pred + predOff + (size_t)t*DYNC;
    float x1b = anchor[(n*4 + 0)*HW + rem] + p[0];
    float y1b = anchor[(n*4 + 1)*HW + rem] + p[1];
    float x2b = anchor[(n*4 + 2)*HW + rem] + p[2];
    float y2b = anchor[(n*4 + 3)*HW + rem] + p[3];
    float cx = 0.5f*(x1b + x2b), cy = 0.5f*(y1b + y2b);
    float th_h = (y2b - y1b)*0.25f;
    float th_w = (x2b - x1b)*0.25f;
    float b0 = p[4], b1 = p[5], b2 = p[6], b3 = p[7];
    float bc0 = b0 - (fmaxf(b0 - th_h, 0.f) + fminf(b0 + th_h, 0.f));
    float bc1 = b1 - (fmaxf(b1 - th_w, 0.f) + fminf(b1 + th_w, 0.f));
    float bc2 = b2 - (fmaxf(b2 - th_h, 0.f) + fminf(b2 + th_h, 0.f));
    float bc3 = b3 - (fmaxf(b3 - th_w, 0.f) + fminf(b3 + th_w, 0.f));

    float ptx[4] = {x1b, cx + bc1, x2b, cx + bc3};
    float pty[4] = {cy + bc0, y1b, cy + bc2, y2b};

    const float* rm = g_regmap + regOff + (size_t)n*HW*4;
    float r[4];
    #pragma unroll
    for (int pc = 0; pc < 4; pc++)
        r[pc] = bilin4(rm, H, W, ptx[pc], pty[pc], pc);

    if (isL1) {
        const float* rml = g_regmap + (size_t)n*HW0*4;
        #pragma unroll
        for (int pc = 0; pc < 4; pc++) {
            float rl = 0.5f*bilin4(rml, H0c, W0c, 2.f*ptx[pc], 2.f*pty[pc], pc);
            float al = p[26 + 2*pc], ah = p[27 + 2*pc];
            float m = fmaxf(al, ah);
            float el = expf(al - m), eh = expf(ah - m);
            float inv = 1.f/(el + eh);
            r[pc] = (el*rl + eh*r[pc])*inv;
        }
    }

    out_coarse[(n*4 + 0)*HW + rem] = x1b;
    out_coarse[(n*4 + 1)*HW + rem] = y1b;
    out_coarse[(n*4 + 2)*HW + rem] = x2b;
    out_coarse[(n*4 + 3)*HW + rem] = y2b;
    out_regbox[(n*4 + 0)*HW + rem] = x1b + r[0];
    out_regbox[(n*4 + 1)*HW + rem] = y1b + r[1];
    out_regbox[(n*4 + 2)*HW + rem] = x2b + r[2];
    out_regbox[(n*4 + 3)*HW + rem] = y2b + r[3];
}

// ---------------- cls sampling ----------------
__global__ void cls_sample_kernel(const float* __restrict__ coarse,
                                  const float* __restrict__ cls_b,
                                  int H, int W, int predOff, size_t clsOff,
                                  float* __restrict__ out)
{
    int t = blockIdx.x;
    int HW = H*W;
    int n = t / HW;
    int rem = t - n*HW;

    const float* p = g_pred + predOff + (size_t)t*DYNC;
    float x1b = coarse[(n*4 + 0)*HW + rem];
    float y1b = coarse[(n*4 + 1)*HW + rem];
    float x2b = coarse[(n*4 + 2)*HW + rem];
    float y2b = coarse[(n*4 + 3)*HW + rem];
    float X[3] = {x1b, 0.5f*(x1b + x2b), x2b};
    float Y[3] = {y1b, 0.5f*(y1b + y2b), y2b};

    int cls = threadIdx.x;
    float acc = cls_b[cls];
    const float* cm = g_clsmap + clsOff + (size_t)n*HW*CLSC;

    #pragma unroll
    for (int pt = 0; pt < 9; pt++) {
        float px = X[pt/3] + p[8 + 2*pt];
        float py = Y[pt%3] + p[9 + 2*pt];
        px = fminf(fmaxf(px, 0.f), (float)(W - 1));
        py = fminf(fmaxf(py, 0.f), (float)(H - 1));
        float xf = floorf(px), yf = floorf(py);
        float fx = px - xf, fy = py - yf;
        int x0 = (int)xf, y0 = (int)yf;
        int x1i = min(x0 + 1, W - 1), y1i = min(y0 + 1, H - 1);
        int chn = pt*NCLS + cls;
        float v00 = cm[(size_t)(y0*W  + x0 )*CLSC + chn];
        float v01 = cm[(size_t)(y0*W  + x1i)*CLSC + chn];
        float v10 = cm[(size_t)(y1i*W + x0 )*CLSC + chn];
        float v11 = cm[(size_t)(y1i*W + x1i)*CLSC + chn];
        acc += v00*(1.f-fx)*(1.f-fy) + v01*fx*(1.f-fy)
             + v10*(1.f-fx)*fy       + v11*fx*fy;
    }
    out[((size_t)(n*NCLS + cls))*HW + rem] = acc;
}

// ---------------- launch ----------------
extern "C" void kernel_launch(void* const* d_in, const int* in_sizes, int n_in,
                              void* d_out, int out_size)
{
    (void)in_sizes; (void)n_in; (void)out_size;
    const float* reg_feat0 = (const float*)d_in[0];
    const float* reg_feat1 = (const float*)d_in[1];
    const float* cls_feat0 = (const float*)d_in[2];
    const float* cls_feat1 = (const float*)d_in[3];
    const float* anchor0   = (const float*)d_in[4];
    const float* anchor1   = (const float*)d_in[5];
    const float* dyn_w     = (const float*)d_in[6];
    const float* dyn_b     = (const float*)d_in[7];
    const float* reg_w     = (const float*)d_in[8];
    const float* cls_w     = (const float*)d_in[9];
    const float* cls_b     = (const float*)d_in[10];
    float* out = (float*)d_out;

    // dyn path prep
    {
        size_t tot = ((size_t)PADTOT*KSPLIT)/8;
        zero_regS_kernel<<<(unsigned)((tot + 255)/256), 256>>>();
    }
    split_reg_kernel<<<dim3((HW0+31)/32, 8, NB), dim3(32,8)>>>(reg_feat0, HW0, 0);
    split_reg_kernel<<<dim3((HW1+31)/32, 8, NB), dim3(32,8)>>>(reg_feat1, HW1, 1);
    split_wdyn_kernel<<<(64*9*256 + 255)/256, 256>>>(dyn_w, reg_w);

    // cls path prep
    split_wcls_kernel<<<(OCP*CIN + 255)/256, 256>>>(cls_w);
    split_feat_kernel<<<dim3((HW0+31)/32, 8, NB), dim3(32,8)>>>(cls_feat0, HW0, 0);
    split_feat_kernel<<<dim3((HW1+31)/32, 8, NB), dim3(32,8)>>>(cls_feat1, HW1, 1);
    zero_pad_feat_kernel<<<((NPIXP-NPIX)*KSPLIT + 255)/256, 256>>>();

    // GEMMs
    dyn_mma_kernel<<<330, 256>>>(dyn_b);
    cls_mma_kernel<<<dim3(297, 6), 256>>>();

    // geometry + sampling
    geom_kernel<<<(NB*HW0 + 255)/256, 256>>>(
        anchor0, H0c, W0c, 0, 0, 0, out + O_CO0, out + O_RB0);
    geom_kernel<<<(NB*HW1 + 255)/256, 256>>>(
        anchor1, H1c, W1c, PRED_OFF1, REG_OFF1, 1, out + O_CO1, out + O_RB1);

    cls_sample_kernel<<<NB*HW0, NCLS>>>(
        out + O_CO0, cls_b, H0c, W0c, 0, (size_t)0, out + O_CLS0);
    cls_sample_kernel<<<NB*HW1, NCLS>>>(
        out + O_CO1, cls_b, H1c, W1c, PRED_OFF1, CLS_OFF1, out + O_CLS1);
}

// round 7
// speedup vs baseline: 3.9324x; 1.2510x over previous
#include <cuda_runtime.h>
#include <cuda_bf16.h>
#include <cstdint>

#define H0c 100
#define W0c 152
#define H1c 50
#define W1c 76
#define HW0 (H0c*W0c)          // 15200
#define HW1 (H1c*W1c)          // 3800
#define NB 2
#define CIN 256
#define DYNC 34
#define CLSC 720
#define NCLS 80
#define NPIX (NB*(HW0+HW1))    // 38000
#define NPIXP 38016            // 297*128
#define KSPLIT 768             // 3*CIN
#define OCP 768
#define KDYN 6912              // 9*768

// padded (H+2, W+2) dims for dyn GEMM A-matrix
#define PH0 102
#define PW0 154
#define PH1 52
#define PW1 78
#define PAD0TOT (NB*PH0*PW0)            // 31416
#define PADTOT (PAD0TOT + NB*PH1*PW1)   // 39528

#define PRED_OFF1 (NB*HW0*DYNC)
#define REG_OFF1  (NB*HW0*4)
#define CLS_OFF1  ((size_t)NB*HW0*CLSC)

#define O_CLS0 0
#define O_CLS1 (NB*NCLS*HW0)
#define O_CO0  (O_CLS1 + NB*NCLS*HW1)
#define O_CO1  (O_CO0 + NB*4*HW0)
#define O_RB0  (O_CO1 + NB*4*HW1)
#define O_RB1  (O_RB0 + NB*4*HW0)

// ---------------- scratch ----------------
__device__ float g_pred[NB*(HW0+HW1)*DYNC];
__device__ float g_regmap[NB*(HW0+HW1)*4];
__device__ float g_clsmap[(size_t)NPIXP*CLSC];
__device__ __align__(16) __nv_bfloat16 g_featS[(size_t)NPIXP*KSPLIT];
__device__ __align__(16) __nv_bfloat16 g_wclsS[(size_t)OCP*KSPLIT];
__device__ __align__(16) __nv_bfloat16 g_regS[(size_t)PADTOT*KSPLIT];
__device__ __align__(16) __nv_bfloat16 g_wdynS[64*KDYN];

// ---------------- PTX helpers ----------------
__device__ __forceinline__ void cpa16(uint32_t d, const void* s) {
    asm volatile("cp.async.cg.shared.global [%0],[%1],16;\n" :: "r"(d), "l"(s));
}
#define CP_COMMIT() asm volatile("cp.async.commit_group;\n")
#define CP_WAIT1()  asm volatile("cp.async.wait_group 1;\n")
#define CP_WAIT0()  asm volatile("cp.async.wait_group 0;\n")

__device__ __forceinline__ void ldm_x4(uint32_t& r0, uint32_t& r1,
                                       uint32_t& r2, uint32_t& r3, uint32_t addr) {
    asm volatile("ldmatrix.sync.aligned.m8n8.x4.shared.b16 {%0,%1,%2,%3},[%4];"
                 : "=r"(r0), "=r"(r1), "=r"(r2), "=r"(r3) : "r"(addr));
}
__device__ __forceinline__ void mma_bf16(float* c, uint32_t a0, uint32_t a1,
                                         uint32_t a2, uint32_t a3,
                                         uint32_t b0, uint32_t b1) {
    asm volatile("mma.sync.aligned.m16n8k16.row.col.f32.bf16.bf16.f32 "
                 "{%0,%1,%2,%3},{%4,%5,%6,%7},{%8,%9},{%0,%1,%2,%3};"
                 : "+f"(c[0]), "+f"(c[1]), "+f"(c[2]), "+f"(c[3])
                 : "r"(a0), "r"(a1), "r"(a2), "r"(a3), "r"(b0), "r"(b1));
}

// ---------------- zero misc: g_regS borders + g_featS tail ----------------
__global__ void zero_misc_kernel() {
    int i = blockIdx.x*blockDim.x + threadIdx.x;
    const int regTot = PADTOT*96;
    if (i < regTot) {
        int pix = i / 96;
        int u = i - pix*96;
        int border;
        if (pix < PAD0TOT) {
            int rem = pix % (PH0*PW0);
            int yy = rem / PW0, xx = rem - yy*PW0;
            border = (yy == 0) | (yy == PH0-1) | (xx == 0) | (xx == PW0-1);
        } else {
            int rem = (pix - PAD0TOT) % (PH1*PW1);
            int yy = rem / PW1, xx = rem - yy*PW1;
            border = (yy == 0) | (yy == PH1-1) | (xx == 0) | (xx == PW1-1);
        }
        if (border)
            ((uint4*)g_regS)[(size_t)pix*96 + u] = make_uint4(0,0,0,0);
    } else if (i < regTot + 16*96) {
        int j = i - regTot;
        ((uint4*)g_featS)[(size_t)NPIX*96 + j] = make_uint4(0,0,0,0);
    }
}

// ---------------- merged weight split ----------------
__global__ void split_w_kernel(const float* __restrict__ dyn_w,
                               const float* __restrict__ reg_w,
                               const float* __restrict__ cls_w) {
    int i = blockIdx.x*blockDim.x + threadIdx.x;
    if (i < 64*9*256) {
        int oc = i / (9*256);
        int rem = i - oc*9*256;
        int p = rem >> 8, c = rem & 255;
        float v = 0.f;
        if (oc < DYNC) v = dyn_w[(oc*CIN + c)*9 + p];
        else if (oc < 38 && p == 4) v = reg_w[(oc - DYNC)*CIN + c];
        __nv_bfloat16 h = __float2bfloat16(v);
        __nv_bfloat16 l = __float2bfloat16(v - __bfloat162float(h));
        size_t o = (size_t)oc*KDYN + p*KSPLIT + c;
        g_wdynS[o] = h;
        g_wdynS[o + 256] = h;
        g_wdynS[o + 512] = l;
    } else {
        int j = i - 64*9*256;
        if (j >= OCP*CIN) return;
        int oc = j >> 8, c = j & 255;
        size_t o = (size_t)oc*KSPLIT + c;
        if (oc < CLSC) {
            float v = cls_w[j];
            __nv_bfloat16 h = __float2bfloat16(v);
            __nv_bfloat16 l = __float2bfloat16(v - __bfloat162float(h));
            g_wclsS[o] = h;
            g_wclsS[o + 256] = h;
            g_wclsS[o + 512] = l;
        } else {
            __nv_bfloat16 z = __float2bfloat16(0.f);
            g_wclsS[o] = z; g_wclsS[o + 256] = z; g_wclsS[o + 512] = z;
        }
    }
}

// ---------------- merged feature transpose+split (4 tensors) ----------------
// blockIdx.z: src = z>>1 (0 reg0, 1 reg1, 2 cls0, 3 cls1), n = z&1
__global__ void split_all_kernel(const float* __restrict__ reg0,
                                 const float* __restrict__ reg1,
                                 const float* __restrict__ cls0,
                                 const float* __restrict__ cls1)
{
    __shared__ float t[32][33];
    int src = blockIdx.z >> 1;
    int n   = blockIdx.z & 1;
    int lvl = src & 1;
    int HW  = lvl ? HW1 : HW0;
    int pixbase = blockIdx.x*32;
    if (pixbase >= HW) return;
    const float* in = (src == 0) ? reg0 : (src == 1) ? reg1 : (src == 2) ? cls0 : cls1;

    int tx = threadIdx.x, ty = threadIdx.y;
    int chbase = blockIdx.y*32;
    int pix = pixbase + tx;
    #pragma unroll
    for (int j = 0; j < 4; j++) {
        int ch = ty + j*8;
        t[ch][tx] = (pix < HW) ? in[((size_t)(n*CIN + chbase + ch))*HW + pix] : 0.f;
    }
    __syncthreads();

    if (src >= 2) {   // cls -> g_featS [gpix][768]
        int base = lvl ? (NB*HW0 + n*HW1) : (n*HW0);
        #pragma unroll
        for (int j = 0; j < 4; j++) {
            int pr = ty + j*8;
            int opix = pixbase + pr;
            if (opix < HW) {
                float v = t[tx][pr];
                __nv_bfloat16 h = __float2bfloat16(v);
                __nv_bfloat16 l = __float2bfloat16(v - __bfloat162float(h));
                size_t o = (size_t)(base + opix)*KSPLIT + chbase + tx;
                g_featS[o] = h;
                g_featS[o + 256] = l;
                g_featS[o + 512] = h;
            }
        }
    } else {          // reg -> g_regS padded [padpix][768]
        int W  = lvl ? W1c : W0c;
        int PW = lvl ? PW1 : PW0;
        int padBase = lvl ? (PAD0TOT + n*PH1*PW1) : (n*PH0*PW0);
        #pragma unroll
        for (int j = 0; j < 4; j++) {
            int pr = ty + j*8;
            int opix = pixbase + pr;
            if (opix < HW) {
                int y = opix / W, x = opix - y*W;
                float v = t[tx][pr];
                __nv_bfloat16 h = __float2bfloat16(v);
                __nv_bfloat16 l = __float2bfloat16(v - __bfloat162float(h));
                size_t o = (size_t)(padBase + (y+1)*PW + x + 1)*KSPLIT + chbase + tx;
                g_regS[o] = h;
                g_regS[o + 256] = l;
                g_regS[o + 512] = h;
            }
        }
    }
}

// ---------------- unified MMA kernel ----------------
// blocks [0,330): dyn implicit GEMM; blocks [330, 2112): cls GEMM
// BK=64, smem row stride 144 B (72 bf16)
#define RS 144
#define DYN_A_STG (128*RS)   // 18432
#define DYN_B_STG (64*RS)    // 9216
#define CLS_A_STG (128*RS)
#define CLS_B_STG (128*RS)
#define UK_SMEM (2*CLS_A_STG + 2*CLS_B_STG)   // 73728

__global__ void __launch_bounds__(256) mma_all_kernel(const float* __restrict__ dyn_b)
{
    extern __shared__ __align__(16) char sm[];
    int tid = threadIdx.x;
    int lane = tid & 31, wid = tid >> 5;
    int wm = wid & 1, wn = wid >> 1;
    int rA = tid >> 3, cA = tid & 7;   // staging row/col

    if (blockIdx.x < 330) {
        // ---------- dyn ----------
        int bid = blockIdx.x;
        int lvl, n, tX, tY;
        if (bid < 260) { lvl = 0; n = bid/130; int t = bid - n*130; tY = t/10; tX = t - tY*10; }
        else { int b = bid - 260; lvl = 1; n = b/35; int t = b - n*35; tY = t/5; tX = t - tY*5; }
        int H  = lvl ? H1c : H0c;
        int W  = lvl ? W1c : W0c;
        int PW = lvl ? PW1 : PW0;
        int padBase = lvl ? (PAD0TOT + n*PH1*PW1) : (n*PH0*PW0);
        int gbase   = lvl ? (NB*HW0 + n*HW1) : (n*HW0);
        int y0 = tY*8, x0 = tX*16;

        int aPix[4];
        #pragma unroll
        for (int j = 0; j < 4; j++) {
            int r = rA + 32*j;
            int y = y0 + (r >> 4); if (y >= H) y = H - 1;
            int x = x0 + (r & 15); if (x >= W) x = W - 1;
            aPix[j] = padBase + (y + 1)*PW + x + 1;
        }

        uint32_t AsB = (uint32_t)__cvta_generic_to_shared(sm);
        uint32_t BsB = AsB + 2*DYN_A_STG;

        float acc[4][2][4];
        #pragma unroll
        for (int f = 0; f < 4; f++)
            #pragma unroll
            for (int j = 0; j < 2; j++)
                #pragma unroll
                for (int e = 0; e < 4; e++) acc[f][j][e] = 0.f;

        #define DYN_LOAD(s, q) do { \
            int p_ = (q)/12, kc_ = (q) - p_*12; \
            int sh_ = (p_/3 - 1)*PW + (p_ - (p_/3)*3 - 1); \
            int ko_ = kc_*64 + cA*8; \
            _Pragma("unroll") \
            for (int j_ = 0; j_ < 4; j_++) \
                cpa16(AsB + (s)*DYN_A_STG + (uint32_t)((rA + 32*j_)*RS + cA*16), \
                      g_regS + (size_t)(aPix[j_] + sh_)*KSPLIT + ko_); \
            _Pragma("unroll") \
            for (int j_ = 0; j_ < 2; j_++) \
                cpa16(BsB + (s)*DYN_B_STG + (uint32_t)((rA + 32*j_)*RS + cA*16), \
                      g_wdynS + (size_t)(rA + 32*j_)*KDYN + p_*KSPLIT + ko_); \
        } while (0)

        DYN_LOAD(0, 0);
        CP_COMMIT();

        #pragma unroll 1
        for (int q = 0; q < 108; q++) {
            int cur = q & 1;
            if (q < 107) {
                DYN_LOAD(cur ^ 1, q + 1);
                CP_COMMIT();
                CP_WAIT1();
            } else {
                CP_WAIT0();
            }
            __syncthreads();

            uint32_t abase = AsB + cur*DYN_A_STG + (uint32_t)((wm*64 + (lane & 15))*RS);
            uint32_t bbase = BsB + cur*DYN_B_STG + (uint32_t)((wn*16 + (lane & 15))*RS);
            uint32_t cofs0 = (uint32_t)((lane >> 4)*16);

            #pragma unroll
            for (int kk = 0; kk < 4; kk++) {
                uint32_t co = cofs0 + kk*32;
                uint32_t a[4][4];
                #pragma unroll
                for (int f = 0; f < 4; f++)
                    ldm_x4(a[f][0], a[f][1], a[f][2], a[f][3], abase + f*16*RS + co);
                uint32_t b[4];
                ldm_x4(b[0], b[1], b[2], b[3], bbase + co);
                #pragma unroll
                for (int f = 0; f < 4; f++) {
                    mma_bf16(acc[f][0], a[f][0], a[f][1], a[f][2], a[f][3], b[0], b[2]);
                    mma_bf16(acc[f][1], a[f][0], a[f][1], a[f][2], a[f][3], b[1], b[3]);
                }
            }
            __syncthreads();
        }

        int rowin = lane >> 2;
        int colin = (lane & 3)*2;
        #pragma unroll
        for (int f = 0; f < 4; f++) {
            #pragma unroll
            for (int half = 0; half < 2; half++) {
                int tr = wm*64 + f*16 + rowin + half*8;
                int y = y0 + (tr >> 4), x = x0 + (tr & 15);
                if (y < H && x < W) {
                    int gp = gbase + y*W + x;
                    #pragma unroll
                    for (int j = 0; j < 2; j++) {
                        int oc = wn*16 + j*8 + colin;
                        float v0 = acc[f][j][half*2];
                        float v1 = acc[f][j][half*2 + 1];
                        if (oc < DYNC) {
                            g_pred[(size_t)gp*DYNC + oc] = v0 + __ldg(dyn_b + oc);
                        } else if (oc < 38) {
                            g_regmap[(size_t)gp*4 + oc - DYNC] = v0;
                        }
                        int oc1 = oc + 1;
                        if (oc1 < DYNC) {
                            g_pred[(size_t)gp*DYNC + oc1] = v1 + __ldg(dyn_b + oc1);
                        } else if (oc1 < 38) {
                            g_regmap[(size_t)gp*4 + oc1 - DYNC] = v1;
                        }
                    }
                }
            }
        }
    } else {
        // ---------- cls ----------
        int bid = blockIdx.x - 330;
        int pixblk = bid % 297;
        int ocblk  = bid / 297;
        int pixbase = pixblk*128;
        int ocbase  = ocblk*128;

        const __nv_bfloat16* Ag = g_featS + (size_t)pixbase*KSPLIT;
        const __nv_bfloat16* Bg = g_wclsS + (size_t)ocbase*KSPLIT;

        uint32_t AsB = (uint32_t)__cvta_generic_to_shared(sm);
        uint32_t BsB = AsB + 2*CLS_A_STG;

        float acc[4][4][4];
        #pragma unroll
        for (int f = 0; f < 4; f++)
            #pragma unroll
            for (int j = 0; j < 4; j++)
                #pragma unroll
                for (int e = 0; e < 4; e++) acc[f][j][e] = 0.f;

        #define CLS_LOAD(s, k0) do { \
            _Pragma("unroll") \
            for (int j_ = 0; j_ < 4; j_++) { \
                cpa16(AsB + (s)*CLS_A_STG + (uint32_t)((rA + 32*j_)*RS + cA*16), \
                      Ag + (size_t)(rA + 32*j_)*KSPLIT + (k0) + cA*8); \
                cpa16(BsB + (s)*CLS_B_STG + (uint32_t)((rA + 32*j_)*RS + cA*16), \
                      Bg + (size_t)(rA + 32*j_)*KSPLIT + (k0) + cA*8); \
            } \
        } while (0)

        CLS_LOAD(0, 0);
        CP_COMMIT();

        #pragma unroll 1
        for (int bk = 0; bk < 12; bk++) {
            int cur = bk & 1;
            if (bk < 11) {
                CLS_LOAD(cur ^ 1, (bk + 1)*64);
                CP_COMMIT();
                CP_WAIT1();
            } else {
                CP_WAIT0();
            }
            __syncthreads();

            uint32_t abase = AsB + cur*CLS_A_STG + (uint32_t)((wm*64 + (lane & 15))*RS);
            uint32_t bbase = BsB + cur*CLS_B_STG + (uint32_t)((wn*32 + (lane & 15))*RS);
            uint32_t cofs0 = (uint32_t)((lane >> 4)*16);

            #pragma unroll
            for (int kk = 0; kk < 4; kk++) {
                uint32_t co = cofs0 + kk*32;
                uint32_t a[4][4];
                #pragma unroll
                for (int f = 0; f < 4; f++)
                    ldm_x4(a[f][0], a[f][1], a[f][2], a[f][3], abase + f*16*RS + co);
                uint32_t b[2][4];
                #pragma unroll
                for (int g = 0; g < 2; g++)
                    ldm_x4(b[g][0], b[g][1], b[g][2], b[g][3], bbase + g*16*RS + co);
                #pragma unroll
                for (int f = 0; f < 4; f++) {
                    #pragma unroll
                    for (int g = 0; g < 2; g++) {
                        mma_bf16(acc[f][2*g],   a[f][0], a[f][1], a[f][2], a[f][3],
                                 b[g][0], b[g][2]);
                        mma_bf16(acc[f][2*g+1], a[f][0], a[f][1], a[f][2], a[f][3],
                                 b[g][1], b[g][3]);
                    }
                }
            }
            __syncthreads();
        }

        int rowin = lane >> 2;
        int colin = (lane & 3)*2;
        #pragma unroll
        for (int f = 0; f < 4; f++) {
            int pix = pixbase + wm*64 + f*16 + rowin;
            #pragma unroll
            for (int j = 0; j < 4; j++) {
                int oc = ocbase + wn*32 + j*8 + colin;
                if (oc < CLSC) {
                    float* d0 = g_clsmap + (size_t)pix*CLSC + oc;
                    d0[0] = acc[f][j][0];
                    d0[1] = acc[f][j][1];
                    float* d1 = g_clsmap + (size_t)(pix + 8)*CLSC + oc;
                    d1[0] = acc[f][j][2];
                    d1[1] = acc[f][j][3];
                }
            }
        }
    }
}

// ---------------- geometry + reg sampling ----------------
__device__ __forceinline__ float bilin4(const float* __restrict__ rm,
                                        int H, int W, float px, float py, int chn)
{
    px = fminf(fmaxf(px, 0.f), (float)(W - 1));
    py = fminf(fmaxf(py, 0.f), (float)(H - 1));
    float xf = floorf(px), yf = floorf(py);
    float fx = px - xf, fy = py - yf;
    int x0 = (int)xf, y0 = (int)yf;
    int x1 = min(x0 + 1, W - 1), y1 = min(y0 + 1, H - 1);
    float v00 = rm[(y0*W + x0)*4 + chn];
    float v01 = rm[(y0*W + x1)*4 + chn];
    float v10 = rm[(y1*W + x0)*4 + chn];
    float v11 = rm[(y1*W + x1)*4 + chn];
    return v00*(1.f-fx)*(1.f-fy) + v01*fx*(1.f-fy)
         + v10*(1.f-fx)*fy       + v11*fx*fy;
}

__global__ void geom_kernel(const float* __restrict__ anchor,
                            int H, int W, int predOff, int regOff, int isL1,
                            float* __restrict__ out_coarse,
                            float* __restrict__ out_regbox)
{
    int t = blockIdx.x*blockDim.x + threadIdx.x;
    int HW = H*W;
    if (t >= NB*HW) return;
    int n = t / HW;
    int rem = t - n*HW;

    const float* p = g_pred + predOff + (size_t)t*DYNC;
    float x1b = anchor[(n*4 + 0)*HW + rem] + p[0];
    float y1b = anchor[(n*4 + 1)*HW + rem] + p[1];
    float x2b = anchor[(n*4 + 2)*HW + rem] + p[2];
    float y2b = anchor[(n*4 + 3)*HW + rem] + p[3];
    float cx = 0.5f*(x1b + x2b), cy = 0.5f*(y1b + y2b);
    float th_h = (y2b - y1b)*0.25f;
    float th_w = (x2b - x1b)*0.25f;
    float b0 = p[4], b1 = p[5], b2 = p[6], b3 = p[7];
    float bc0 = b0 - (fmaxf(b0 - th_h, 0.f) + fminf(b0 + th_h, 0.f));
    float bc1 = b1 - (fmaxf(b1 - th_w, 0.f) + fminf(b1 + th_w, 0.f));
    float bc2 = b2 - (fmaxf(b2 - th_h, 0.f) + fminf(b2 + th_h, 0.f));
    float bc3 = b3 - (fmaxf(b3 - th_w, 0.f) + fminf(b3 + th_w, 0.f));

    float ptx[4] = {x1b, cx + bc1, x2b, cx + bc3};
    float pty[4] = {cy + bc0, y1b, cy + bc2, y2b};

    const float* rm = g_regmap + regOff + (size_t)n*HW*4;
    float r[4];
    #pragma unroll
    for (int pc = 0; pc < 4; pc++)
        r[pc] = bilin4(rm, H, W, ptx[pc], pty[pc], pc);

    if (isL1) {
        const float* rml = g_regmap + (size_t)n*HW0*4;
        #pragma unroll
        for (int pc = 0; pc < 4; pc++) {
            float rl = 0.5f*bilin4(rml, H0c, W0c, 2.f*ptx[pc], 2.f*pty[pc], pc);
            float al = p[26 + 2*pc], ah = p[27 + 2*pc];
            float m = fmaxf(al, ah);
            float el = expf(al - m), eh = expf(ah - m);
            float inv = 1.f/(el + eh);
            r[pc] = (el*rl + eh*r[pc])*inv;
        }
    }

    out_coarse[(n*4 + 0)*HW + rem] = x1b;
    out_coarse[(n*4 + 1)*HW + rem] = y1b;
    out_coarse[(n*4 + 2)*HW + rem] = x2b;
    out_coarse[(n*4 + 3)*HW + rem] = y2b;
    out_regbox[(n*4 + 0)*HW + rem] = x1b + r[0];
    out_regbox[(n*4 + 1)*HW + rem] = y1b + r[1];
    out_regbox[(n*4 + 2)*HW + rem] = x2b + r[2];
    out_regbox[(n*4 + 3)*HW + rem] = y2b + r[3];
}

// ---------------- cls sampling ----------------
__global__ void cls_sample_kernel(const float* __restrict__ coarse,
                                  const float* __restrict__ cls_b,
                                  int H, int W, int predOff, size_t clsOff,
                                  float* __restrict__ out)
{
    int t = blockIdx.x;
    int HW = H*W;
    int n = t / HW;
    int rem = t - n*HW;

    const float* p = g_pred + predOff + (size_t)t*DYNC;
    float x1b = coarse[(n*4 + 0)*HW + rem];
    float y1b = coarse[(n*4 + 1)*HW + rem];
    float x2b = coarse[(n*4 + 2)*HW + rem];
    float y2b = coarse[(n*4 + 3)*HW + rem];
    float X[3] = {x1b, 0.5f*(x1b + x2b), x2b};
    float Y[3] = {y1b, 0.5f*(y1b + y2b), y2b};

    int cls = threadIdx.x;
    float acc = cls_b[cls];
    const float* cm = g_clsmap + clsOff + (size_t)n*HW*CLSC;

    #pragma unroll
    for (int pt = 0; pt < 9; pt++) {
        float px = X[pt/3] + p[8 + 2*pt];
        float py = Y[pt%3] + p[9 + 2*pt];
        px = fminf(fmaxf(px, 0.f), (float)(W - 1));
        py = fminf(fmaxf(py, 0.f), (float)(H - 1));
        float xf = floorf(px), yf = floorf(py);
        float fx = px - xf, fy = py - yf;
        int x0 = (int)xf, y0 = (int)yf;
        int x1i = min(x0 + 1, W - 1), y1i = min(y0 + 1, H - 1);
        int chn = pt*NCLS + cls;
        float v00 = cm[(size_t)(y0*W  + x0 )*CLSC + chn];
        float v01 = cm[(size_t)(y0*W  + x1i)*CLSC + chn];
        float v10 = cm[(size_t)(y1i*W + x0 )*CLSC + chn];
        float v11 = cm[(size_t)(y1i*W + x1i)*CLSC + chn];
        acc += v00*(1.f-fx)*(1.f-fy) + v01*fx*(1.f-fy)
             + v10*(1.f-fx)*fy       + v11*fx*fy;
    }
    out[((size_t)(n*NCLS + cls))*HW + rem] = acc;
}

// ---------------- launch ----------------
extern "C" void kernel_launch(void* const* d_in, const int* in_sizes, int n_in,
                              void* d_out, int out_size)
{
    (void)in_sizes; (void)n_in; (void)out_size;
    const float* reg_feat0 = (const float*)d_in[0];
    const float* reg_feat1 = (const float*)d_in[1];
    const float* cls_feat0 = (const float*)d_in[2];
    const float* cls_feat1 = (const float*)d_in[3];
    const float* anchor0   = (const float*)d_in[4];
    const float* anchor1   = (const float*)d_in[5];
    const float* dyn_w     = (const float*)d_in[6];
    const float* dyn_b     = (const float*)d_in[7];
    const float* reg_w     = (const float*)d_in[8];
    const float* cls_w     = (const float*)d_in[9];
    const float* cls_b     = (const float*)d_in[10];
    float* out = (float*)d_out;

    static int attrSet = 0;
    if (!attrSet) {
        cudaFuncSetAttribute(mma_all_kernel,
                             cudaFuncAttributeMaxDynamicSharedMemorySize, UK_SMEM);
        attrSet = 1;
    }

    zero_misc_kernel<<<(PADTOT*96 + 16*96 + 255)/256, 256>>>();
    split_all_kernel<<<dim3(475, 8, 8), dim3(32, 8)>>>(
        reg_feat0, reg_feat1, cls_feat0, cls_feat1);
    split_w_kernel<<<(64*9*256 + OCP*CIN + 255)/256, 256>>>(dyn_w, reg_w, cls_w);

    mma_all_kernel<<<2112, 256, UK_SMEM>>>(dyn_b);

    geom_kernel<<<(NB*HW0 + 255)/256, 256>>>(
        anchor0, H0c, W0c, 0, 0, 0, out + O_CO0, out + O_RB0);
    geom_kernel<<<(NB*HW1 + 255)/256, 256>>>(
        anchor1, H1c, W1c, PRED_OFF1, REG_OFF1, 1, out + O_CO1, out + O_RB1);

    cls_sample_kernel<<<NB*HW0, NCLS>>>(
        out + O_CO0, cls_b, H0c, W0c, 0, (size_t)0, out + O_CLS0);
    cls_sample_kernel<<<NB*HW1, NCLS>>>(
        out + O_CO1, cls_b, H1c, W1c, PRED_OFF1, CLS_OFF1, out + O_CLS1);
}

// round 8
// speedup vs baseline: 4.2014x; 1.0684x over previous
#include <cuda_runtime.h>
#include <cuda_bf16.h>
#include <cstdint>

#define H0c 100
#define W0c 152
#define H1c 50
#define W1c 76
#define HW0 (H0c*W0c)          // 15200
#define HW1 (H1c*W1c)          // 3800
#define NB 2
#define CIN 256
#define DYNC 34
#define CLSC 720
#define NCLS 80
#define NPIX (NB*(HW0+HW1))    // 38000
#define NPIXP 38016            // 297*128
#define KSPLIT 768             // 3*CIN
#define OCP 768
#define KDYN 6912              // 9*768

// padded (H+2, W+2) dims for dyn GEMM A-matrix
#define PH0 102
#define PW0 154
#define PH1 52
#define PW1 78
#define PAD0TOT (NB*PH0*PW0)            // 31416
#define PADTOT (PAD0TOT + NB*PH1*PW1)   // 39528

#define PRED_OFF1 (NB*HW0*DYNC)
#define REG_OFF1  (NB*HW0*4)
#define CLS_OFF1  ((size_t)NB*HW0*CLSC)

#define O_CLS0 0
#define O_CLS1 (NB*NCLS*HW0)
#define O_CO0  (O_CLS1 + NB*NCLS*HW1)
#define O_CO1  (O_CO0 + NB*4*HW0)
#define O_RB0  (O_CO1 + NB*4*HW1)
#define O_RB1  (O_RB0 + NB*4*HW0)

// ---------------- scratch ----------------
__device__ float g_pred[NB*(HW0+HW1)*DYNC];
__device__ float g_regmap[NB*(HW0+HW1)*4];
__device__ float g_clsmap[(size_t)NPIXP*CLSC];
__device__ __align__(16) __nv_bfloat16 g_featS[(size_t)NPIXP*KSPLIT];
__device__ __align__(16) __nv_bfloat16 g_wclsS[(size_t)OCP*KSPLIT];
__device__ __align__(16) __nv_bfloat16 g_regS[(size_t)PADTOT*KSPLIT];
__device__ __align__(16) __nv_bfloat16 g_wdynS[64*KDYN];

// ---------------- PTX helpers ----------------
__device__ __forceinline__ void cpa16(uint32_t d, const void* s) {
    asm volatile("cp.async.cg.shared.global [%0],[%1],16;\n" :: "r"(d), "l"(s));
}
#define CP_COMMIT() asm volatile("cp.async.commit_group;\n")
#define CP_WAIT1()  asm volatile("cp.async.wait_group 1;\n")
#define CP_WAIT0()  asm volatile("cp.async.wait_group 0;\n")

__device__ __forceinline__ void ldm_x4(uint32_t& r0, uint32_t& r1,
                                       uint32_t& r2, uint32_t& r3, uint32_t addr) {
    asm volatile("ldmatrix.sync.aligned.m8n8.x4.shared.b16 {%0,%1,%2,%3},[%4];"
                 : "=r"(r0), "=r"(r1), "=r"(r2), "=r"(r3) : "r"(addr));
}
__device__ __forceinline__ void mma_bf16(float* c, uint32_t a0, uint32_t a1,
                                         uint32_t a2, uint32_t a3,
                                         uint32_t b0, uint32_t b1) {
    asm volatile("mma.sync.aligned.m16n8k16.row.col.f32.bf16.bf16.f32 "
                 "{%0,%1,%2,%3},{%4,%5,%6,%7},{%8,%9},{%0,%1,%2,%3};"
                 : "+f"(c[0]), "+f"(c[1]), "+f"(c[2]), "+f"(c[3])
                 : "r"(a0), "r"(a1), "r"(a2), "r"(a3), "r"(b0), "r"(b1));
}

// ---------------- zero misc: g_regS borders + g_featS tail ----------------
__global__ void zero_misc_kernel() {
    int i = blockIdx.x*blockDim.x + threadIdx.x;
    const int regTot = PADTOT*96;
    if (i < regTot) {
        int pix = i / 96;
        int u = i - pix*96;
        int border;
        if (pix < PAD0TOT) {
            int rem = pix % (PH0*PW0);
            int yy = rem / PW0, xx = rem - yy*PW0;
            border = (yy == 0) | (yy == PH0-1) | (xx == 0) | (xx == PW0-1);
        } else {
            int rem = (pix - PAD0TOT) % (PH1*PW1);
            int yy = rem / PW1, xx = rem - yy*PW1;
            border = (yy == 0) | (yy == PH1-1) | (xx == 0) | (xx == PW1-1);
        }
        if (border)
            ((uint4*)g_regS)[(size_t)pix*96 + u] = make_uint4(0,0,0,0);
    } else if (i < regTot + 16*96) {
        int j = i - regTot;
        ((uint4*)g_featS)[(size_t)NPIX*96 + j] = make_uint4(0,0,0,0);
    }
}

// ---------------- merged weight split ----------------
__global__ void split_w_kernel(const float* __restrict__ dyn_w,
                               const float* __restrict__ reg_w,
                               const float* __restrict__ cls_w) {
    int i = blockIdx.x*blockDim.x + threadIdx.x;
    if (i < 64*9*256) {
        int oc = i / (9*256);
        int rem = i - oc*9*256;
        int p = rem >> 8, c = rem & 255;
        float v = 0.f;
        if (oc < DYNC) v = dyn_w[(oc*CIN + c)*9 + p];
        else if (oc < 38 && p == 4) v = reg_w[(oc - DYNC)*CIN + c];
        __nv_bfloat16 h = __float2bfloat16(v);
        __nv_bfloat16 l = __float2bfloat16(v - __bfloat162float(h));
        size_t o = (size_t)oc*KDYN + p*KSPLIT + c;
        g_wdynS[o] = h;
        g_wdynS[o + 256] = h;
        g_wdynS[o + 512] = l;
    } else {
        int j = i - 64*9*256;
        if (j >= OCP*CIN) return;
        int oc = j >> 8, c = j & 255;
        size_t o = (size_t)oc*KSPLIT + c;
        if (oc < CLSC) {
            float v = cls_w[j];
            __nv_bfloat16 h = __float2bfloat16(v);
            __nv_bfloat16 l = __float2bfloat16(v - __bfloat162float(h));
            g_wclsS[o] = h;
            g_wclsS[o + 256] = h;
            g_wclsS[o + 512] = l;
        } else {
            __nv_bfloat16 z = __float2bfloat16(0.f);
            g_wclsS[o] = z; g_wclsS[o + 256] = z; g_wclsS[o + 512] = z;
        }
    }
}

// ---------------- merged feature transpose+split (4 tensors) ----------------
__global__ void split_all_kernel(const float* __restrict__ reg0,
                                 const float* __restrict__ reg1,
                                 const float* __restrict__ cls0,
                                 const float* __restrict__ cls1)
{
    __shared__ float t[32][33];
    int src = blockIdx.z >> 1;
    int n   = blockIdx.z & 1;
    int lvl = src & 1;
    int HW  = lvl ? HW1 : HW0;
    int pixbase = blockIdx.x*32;
    if (pixbase >= HW) return;
    const float* in = (src == 0) ? reg0 : (src == 1) ? reg1 : (src == 2) ? cls0 : cls1;

    int tx = threadIdx.x, ty = threadIdx.y;
    int chbase = blockIdx.y*32;
    int pix = pixbase + tx;
    #pragma unroll
    for (int j = 0; j < 4; j++) {
        int ch = ty + j*8;
        t[ch][tx] = (pix < HW) ? in[((size_t)(n*CIN + chbase + ch))*HW + pix] : 0.f;
    }
    __syncthreads();

    if (src >= 2) {
        int base = lvl ? (NB*HW0 + n*HW1) : (n*HW0);
        #pragma unroll
        for (int j = 0; j < 4; j++) {
            int pr = ty + j*8;
            int opix = pixbase + pr;
            if (opix < HW) {
                float v = t[tx][pr];
                __nv_bfloat16 h = __float2bfloat16(v);
                __nv_bfloat16 l = __float2bfloat16(v - __bfloat162float(h));
                size_t o = (size_t)(base + opix)*KSPLIT + chbase + tx;
                g_featS[o] = h;
                g_featS[o + 256] = l;
                g_featS[o + 512] = h;
            }
        }
    } else {
        int W  = lvl ? W1c : W0c;
        int PW = lvl ? PW1 : PW0;
        int padBase = lvl ? (PAD0TOT + n*PH1*PW1) : (n*PH0*PW0);
        #pragma unroll
        for (int j = 0; j < 4; j++) {
            int pr = ty + j*8;
            int opix = pixbase + pr;
            if (opix < HW) {
                int y = opix / W, x = opix - y*W;
                float v = t[tx][pr];
                __nv_bfloat16 h = __float2bfloat16(v);
                __nv_bfloat16 l = __float2bfloat16(v - __bfloat162float(h));
                size_t o = (size_t)(padBase + (y+1)*PW + x + 1)*KSPLIT + chbase + tx;
                g_regS[o] = h;
                g_regS[o + 256] = l;
                g_regS[o + 512] = h;
            }
        }
    }
}

// ---------------- unified MMA kernel (128 threads, 4 warps) ----------------
// blocks [0,330): dyn (128x64 tile, warp 64x32); [330,2112): cls (128x128, warp 64x64)
#define RS 144
#define A_STG (128*RS)       // 18432
#define DYN_B_STG (64*RS)    // 9216
#define CLS_B_STG (128*RS)   // 18432
#define UK_SMEM (2*A_STG + 2*CLS_B_STG)   // 73728

__global__ void __launch_bounds__(128) mma_all_kernel(const float* __restrict__ dyn_b)
{
    extern __shared__ __align__(16) char sm[];
    int tid = threadIdx.x;
    int lane = tid & 31, wid = tid >> 5;     // 4 warps
    int wm = wid & 1, wn = wid >> 1;         // 2x2
    int rA = tid >> 3, cA = tid & 7;         // staging: 16 rows x 8 cols(16B)

    uint32_t AsB = (uint32_t)__cvta_generic_to_shared(sm);

    if (blockIdx.x < 330) {
        // ---------- dyn: 128x64, warp 64x32 ----------
        int bid = blockIdx.x;
        int lvl, n, tX, tY;
        if (bid < 260) { lvl = 0; n = bid/130; int t = bid - n*130; tY = t/10; tX = t - tY*10; }
        else { int b = bid - 260; lvl = 1; n = b/35; int t = b - n*35; tY = t/5; tX = t - tY*5; }
        int H  = lvl ? H1c : H0c;
        int W  = lvl ? W1c : W0c;
        int PW = lvl ? PW1 : PW0;
        int padBase = lvl ? (PAD0TOT + n*PH1*PW1) : (n*PH0*PW0);
        int gbase   = lvl ? (NB*HW0 + n*HW1) : (n*HW0);
        int y0 = tY*8, x0 = tX*16;

        int aPix[8];
        #pragma unroll
        for (int j = 0; j < 8; j++) {
            int r = rA + 16*j;
            int y = y0 + (r >> 4); if (y >= H) y = H - 1;
            int x = x0 + (r & 15); if (x >= W) x = W - 1;
            aPix[j] = padBase + (y + 1)*PW + x + 1;
        }

        uint32_t BsB = AsB + 2*A_STG;

        float acc[4][4][4];
        #pragma unroll
        for (int f = 0; f < 4; f++)
            #pragma unroll
            for (int j = 0; j < 4; j++)
                #pragma unroll
                for (int e = 0; e < 4; e++) acc[f][j][e] = 0.f;

        #define DYN_LOAD(s, q) do { \
            int p_ = (q)/12, kc_ = (q) - p_*12; \
            int sh_ = (p_/3 - 1)*PW + (p_ - (p_/3)*3 - 1); \
            int ko_ = kc_*64 + cA*8; \
            _Pragma("unroll") \
            for (int j_ = 0; j_ < 8; j_++) \
                cpa16(AsB + (s)*A_STG + (uint32_t)((rA + 16*j_)*RS + cA*16), \
                      g_regS + (size_t)(aPix[j_] + sh_)*KSPLIT + ko_); \
            _Pragma("unroll") \
            for (int j_ = 0; j_ < 4; j_++) \
                cpa16(BsB + (s)*DYN_B_STG + (uint32_t)((rA + 16*j_)*RS + cA*16), \
                      g_wdynS + (size_t)(rA + 16*j_)*KDYN + p_*KSPLIT + ko_); \
        } while (0)

        DYN_LOAD(0, 0);
        CP_COMMIT();

        #pragma unroll 1
        for (int q = 0; q < 108; q++) {
            int cur = q & 1;
            if (q < 107) {
                DYN_LOAD(cur ^ 1, q + 1);
                CP_COMMIT();
                CP_WAIT1();
            } else {
                CP_WAIT0();
            }
            __syncthreads();

            uint32_t abase = AsB + cur*A_STG + (uint32_t)((wm*64 + (lane & 15))*RS);
            uint32_t bbase = BsB + cur*DYN_B_STG + (uint32_t)((wn*32 + (lane & 15))*RS);
            uint32_t cofs0 = (uint32_t)((lane >> 4)*16);

            #pragma unroll
            for (int kk = 0; kk < 4; kk++) {
                uint32_t co = cofs0 + kk*32;
                uint32_t a[4][4];
                #pragma unroll
                for (int f = 0; f < 4; f++)
                    ldm_x4(a[f][0], a[f][1], a[f][2], a[f][3], abase + f*16*RS + co);
                uint32_t b[2][4];
                #pragma unroll
                for (int g = 0; g < 2; g++)
                    ldm_x4(b[g][0], b[g][1], b[g][2], b[g][3], bbase + g*16*RS + co);
                #pragma unroll
                for (int f = 0; f < 4; f++)
                    #pragma unroll
                    for (int g = 0; g < 2; g++) {
                        mma_bf16(acc[f][2*g],   a[f][0], a[f][1], a[f][2], a[f][3],
                                 b[g][0], b[g][2]);
                        mma_bf16(acc[f][2*g+1], a[f][0], a[f][1], a[f][2], a[f][3],
                                 b[g][1], b[g][3]);
                    }
            }
            __syncthreads();
        }

        int rowin = lane >> 2;
        int colin = (lane & 3)*2;
        #pragma unroll
        for (int f = 0; f < 4; f++) {
            #pragma unroll
            for (int half = 0; half < 2; half++) {
                int tr = wm*64 + f*16 + rowin + half*8;
                int y = y0 + (tr >> 4), x = x0 + (tr & 15);
                if (y < H && x < W) {
                    int gp = gbase + y*W + x;
                    #pragma unroll
                    for (int j = 0; j < 4; j++) {
                        int oc = wn*32 + j*8 + colin;
                        float v0 = acc[f][j][half*2];
                        float v1 = acc[f][j][half*2 + 1];
                        if (oc < DYNC) {
                            g_pred[(size_t)gp*DYNC + oc] = v0 + __ldg(dyn_b + oc);
                        } else if (oc < 38) {
                            g_regmap[(size_t)gp*4 + oc - DYNC] = v0;
                        }
                        int oc1 = oc + 1;
                        if (oc1 < DYNC) {
                            g_pred[(size_t)gp*DYNC + oc1] = v1 + __ldg(dyn_b + oc1);
                        } else if (oc1 < 38) {
                            g_regmap[(size_t)gp*4 + oc1 - DYNC] = v1;
                        }
                    }
                }
            }
        }
    } else {
        // ---------- cls: 128x128, warp 64x64 ----------
        int bid = blockIdx.x - 330;
        int pixblk = bid % 297;
        int ocblk  = bid / 297;
        int pixbase = pixblk*128;
        int ocbase  = ocblk*128;

        const __nv_bfloat16* Ag = g_featS + (size_t)pixbase*KSPLIT;
        const __nv_bfloat16* Bg = g_wclsS + (size_t)ocbase*KSPLIT;

        uint32_t BsB = AsB + 2*A_STG;

        float acc[4][8][4];
        #pragma unroll
        for (int f = 0; f < 4; f++)
            #pragma unroll
            for (int j = 0; j < 8; j++)
                #pragma unroll
                for (int e = 0; e < 4; e++) acc[f][j][e] = 0.f;

        #define CLS_LOAD(s, k0) do { \
            _Pragma("unroll") \
            for (int j_ = 0; j_ < 8; j_++) { \
                cpa16(AsB + (s)*A_STG + (uint32_t)((rA + 16*j_)*RS + cA*16), \
                      Ag + (size_t)(rA + 16*j_)*KSPLIT + (k0) + cA*8); \
                cpa16(BsB + (s)*CLS_B_STG + (uint32_t)((rA + 16*j_)*RS + cA*16), \
                      Bg + (size_t)(rA + 16*j_)*KSPLIT + (k0) + cA*8); \
            } \
        } while (0)

        CLS_LOAD(0, 0);
        CP_COMMIT();

        #pragma unroll 1
        for (int bk = 0; bk < 12; bk++) {
            int cur = bk & 1;
            if (bk < 11) {
                CLS_LOAD(cur ^ 1, (bk + 1)*64);
                CP_COMMIT();
                CP_WAIT1();
            } else {
                CP_WAIT0();
            }
            __syncthreads();

            uint32_t abase = AsB + cur*A_STG + (uint32_t)((wm*64 + (lane & 15))*RS);
            uint32_t bbase = BsB + cur*CLS_B_STG + (uint32_t)((wn*64 + (lane & 15))*RS);
            uint32_t cofs0 = (uint32_t)((lane >> 4)*16);

            #pragma unroll
            for (int kk = 0; kk < 4; kk++) {
                uint32_t co = cofs0 + kk*32;
                uint32_t a[4][4];
                #pragma unroll
                for (int f = 0; f < 4; f++)
                    ldm_x4(a[f][0], a[f][1], a[f][2], a[f][3], abase + f*16*RS + co);
                uint32_t b[4][4];
                #pragma unroll
                for (int g = 0; g < 4; g++)
                    ldm_x4(b[g][0], b[g][1], b[g][2], b[g][3], bbase + g*16*RS + co);
                #pragma unroll
                for (int f = 0; f < 4; f++)
                    #pragma unroll
                    for (int g = 0; g < 4; g++) {
                        mma_bf16(acc[f][2*g],   a[f][0], a[f][1], a[f][2], a[f][3],
                                 b[g][0], b[g][2]);
                        mma_bf16(acc[f][2*g+1], a[f][0], a[f][1], a[f][2], a[f][3],
                                 b[g][1], b[g][3]);
                    }
            }
            __syncthreads();
        }

        int rowin = lane >> 2;
        int colin = (lane & 3)*2;
        #pragma unroll
        for (int f = 0; f < 4; f++) {
            int pix = pixbase + wm*64 + f*16 + rowin;
            #pragma unroll
            for (int j = 0; j < 8; j++) {
                int oc = ocbase + wn*64 + j*8 + colin;
                if (oc < CLSC) {
                    float* d0 = g_clsmap + (size_t)pix*CLSC + oc;
                    d0[0] = acc[f][j][0];
                    d0[1] = acc[f][j][1];
                    float* d1 = g_clsmap + (size_t)(pix + 8)*CLSC + oc;
                    d1[0] = acc[f][j][2];
                    d1[1] = acc[f][j][3];
                }
            }
        }
    }
}

// ---------------- geometry + reg sampling ----------------
__device__ __forceinline__ float bilin4(const float* __restrict__ rm,
                                        int H, int W, float px, float py, int chn)
{
    px = fminf(fmaxf(px, 0.f), (float)(W - 1));
    py = fminf(fmaxf(py, 0.f), (float)(H - 1));
    float xf = floorf(px), yf = floorf(py);
    float fx = px - xf, fy = py - yf;
    int x0 = (int)xf, y0 = (int)yf;
    int x1 = min(x0 + 1, W - 1), y1 = min(y0 + 1, H - 1);
    float v00 = rm[(y0*W + x0)*4 + chn];
    float v01 = rm[(y0*W + x1)*4 + chn];
    float v10 = rm[(y1*W + x0)*4 + chn];
    float v11 = rm[(y1*W + x1)*4 + chn];
    return v00*(1.f-fx)*(1.f-fy) + v01*fx*(1.f-fy)
         + v10*(1.f-fx)*fy       + v11*fx*fy;
}

__global__ void geom_kernel(const float* __restrict__ anchor,
                            int H, int W, int predOff, int regOff, int isL1,
                            float* __restrict__ out_coarse,
                            float* __restrict__ out_regbox)
{
    int t = blockIdx.x*blockDim.x + threadIdx.x;
    int HW = H*W;
    if (t >= NB*HW) return;
    int n = t / HW;
    int rem = t - n*HW;

    const float* p = g_pred + predOff + (size_t)t*DYNC;
    float x1b = anchor[(n*4 + 0)*HW + rem] + p[0];
    float y1b = anchor[(n*4 + 1)*HW + rem] + p[1];
    float x2b = anchor[(n*4 + 2)*HW + rem] + p[2];
    float y2b = anchor[(n*4 + 3)*HW + rem] + p[3];
    float cx = 0.5f*(x1b + x2b), cy = 0.5f*(y1b + y2b);
    float th_h = (y2b - y1b)*0.25f;
    float th_w = (x2b - x1b)*0.25f;
    float b0 = p[4], b1 = p[5], b2 = p[6], b3 = p[7];
    float bc0 = b0 - (fmaxf(b0 - th_h, 0.f) + fminf(b0 + th_h, 0.f));
    float bc1 = b1 - (fmaxf(b1 - th_w, 0.f) + fminf(b1 + th_w, 0.f));
    float bc2 = b2 - (fmaxf(b2 - th_h, 0.f) + fminf(b2 + th_h, 0.f));
    float bc3 = b3 - (fmaxf(b3 - th_w, 0.f) + fminf(b3 + th_w, 0.f));

    float ptx[4] = {x1b, cx + bc1, x2b, cx + bc3};
    float pty[4] = {cy + bc0, y1b, cy + bc2, y2b};

    const float* rm = g_regmap + regOff + (size_t)n*HW*4;
    float r[4];
    #pragma unroll
    for (int pc = 0; pc < 4; pc++)
        r[pc] = bilin4(rm, H, W, ptx[pc], pty[pc], pc);

    if (isL1) {
        const float* rml = g_regmap + (size_t)n*HW0*4;
        #pragma unroll
        for (int pc = 0; pc < 4; pc++) {
            float rl = 0.5f*bilin4(rml, H0c, W0c, 2.f*ptx[pc], 2.f*pty[pc], pc);
            float al = p[26 + 2*pc], ah = p[27 + 2*pc];
            float m = fmaxf(al, ah);
            float el = expf(al - m), eh = expf(ah - m);
            float inv = 1.f/(el + eh);
            r[pc] = (el*rl + eh*r[pc])*inv;
        }
    }

    out_coarse[(n*4 + 0)*HW + rem] = x1b;
    out_coarse[(n*4 + 1)*HW + rem] = y1b;
    out_coarse[(n*4 + 2)*HW + rem] = x2b;
    out_coarse[(n*4 + 3)*HW + rem] = y2b;
    out_regbox[(n*4 + 0)*HW + rem] = x1b + r[0];
    out_regbox[(n*4 + 1)*HW + rem] = y1b + r[1];
    out_regbox[(n*4 + 2)*HW + rem] = x2b + r[2];
    out_regbox[(n*4 + 3)*HW + rem] = y2b + r[3];
}

// ---------------- cls sampling ----------------
__global__ void cls_sample_kernel(const float* __restrict__ coarse,
                                  const float* __restrict__ cls_b,
                                  int H, int W, int predOff, size_t clsOff,
                                  float* __restrict__ out)
{
    int t = blockIdx.x;
    int HW = H*W;
    int n = t / HW;
    int rem = t - n*HW;

    const float* p = g_pred + predOff + (size_t)t*DYNC;
    float x1b = coarse[(n*4 + 0)*HW + rem];
    float y1b = coarse[(n*4 + 1)*HW + rem];
    float x2b = coarse[(n*4 + 2)*HW + rem];
    float y2b = coarse[(n*4 + 3)*HW + rem];
    float X[3] = {x1b, 0.5f*(x1b + x2b), x2b};
    float Y[3] = {y1b, 0.5f*(y1b + y2b), y2b};

    int cls = threadIdx.x;
    float acc = cls_b[cls];
    const float* cm = g_clsmap + clsOff + (size_t)n*HW*CLSC;

    #pragma unroll
    for (int pt = 0; pt < 9; pt++) {
        float px = X[pt/3] + p[8 + 2*pt];
        float py = Y[pt%3] + p[9 + 2*pt];
        px = fminf(fmaxf(px, 0.f), (float)(W - 1));
        py = fminf(fmaxf(py, 0.f), (float)(H - 1));
        float xf = floorf(px), yf = floorf(py);
        float fx = px - xf, fy = py - yf;
        int x0 = (int)xf, y0 = (int)yf;
        int x1i = min(x0 + 1, W - 1), y1i = min(y0 + 1, H - 1);
        int chn = pt*NCLS + cls;
        float v00 = cm[(size_t)(y0*W  + x0 )*CLSC + chn];
        float v01 = cm[(size_t)(y0*W  + x1i)*CLSC + chn];
        float v10 = cm[(size_t)(y1i*W + x0 )*CLSC + chn];
        float v11 = cm[(size_t)(y1i*W + x1i)*CLSC + chn];
        acc += v00*(1.f-fx)*(1.f-fy) + v01*fx*(1.f-fy)
             + v10*(1.f-fx)*fy       + v11*fx*fy;
    }
    out[((size_t)(n*NCLS + cls))*HW + rem] = acc;
}

// ---------------- launch ----------------
extern "C" void kernel_launch(void* const* d_in, const int* in_sizes, int n_in,
                              void* d_out, int out_size)
{
    (void)in_sizes; (void)n_in; (void)out_size;
    const float* reg_feat0 = (const float*)d_in[0];
    const float* reg_feat1 = (const float*)d_in[1];
    const float* cls_feat0 = (const float*)d_in[2];
    const float* cls_feat1 = (const float*)d_in[3];
    const float* anchor0   = (const float*)d_in[4];
    const float* anchor1   = (const float*)d_in[5];
    const float* dyn_w     = (const float*)d_in[6];
    const float* dyn_b     = (const float*)d_in[7];
    const float* reg_w     = (const float*)d_in[8];
    const float* cls_w     = (const float*)d_in[9];
    const float* cls_b     = (const float*)d_in[10];
    float* out = (float*)d_out;

    static int attrSet = 0;
    if (!attrSet) {
        cudaFuncSetAttribute(mma_all_kernel,
                             cudaFuncAttributeMaxDynamicSharedMemorySize, UK_SMEM);
        attrSet = 1;
    }

    zero_misc_kernel<<<(PADTOT*96 + 16*96 + 255)/256, 256>>>();
    split_all_kernel<<<dim3(475, 8, 8), dim3(32, 8)>>>(
        reg_feat0, reg_feat1, cls_feat0, cls_feat1);
    split_w_kernel<<<(64*9*256 + OCP*CIN + 255)/256, 256>>>(dyn_w, reg_w, cls_w);

    mma_all_kernel<<<2112, 128, UK_SMEM>>>(dyn_b);

    geom_kernel<<<(NB*HW0 + 255)/256, 256>>>(
        anchor0, H0c, W0c, 0, 0, 0, out + O_CO0, out + O_RB0);
    geom_kernel<<<(NB*HW1 + 255)/256, 256>>>(
        anchor1, H1c, W1c, PRED_OFF1, REG_OFF1, 1, out + O_CO1, out + O_RB1);

    cls_sample_kernel<<<NB*HW0, NCLS>>>(
        out + O_CO0, cls_b, H0c, W0c, 0, (size_t)0, out + O_CLS0);
    cls_sample_kernel<<<NB*HW1, NCLS>>>(
        out + O_CO1, cls_b, H1c, W1c, PRED_OFF1, CLS_OFF1, out + O_CLS1);
}